// round 11
// baseline (speedup 1.0000x reference)
#include <cuda_runtime.h>
#include <cuda_fp16.h>
#include <math.h>
#include <stdint.h>

// ---------------- problem constants ----------------
#define PP   25
#define QQ   2000
#define CC   640
#define SS   25
#define TILE 16000          // CC*SS floats

#define MPAD 640            // Gram rows padded (625 valid)
#define NKC  20             // K chunks of 32 (int8)
#define CHUNK_BYTES (MPAD * 32)   // 640 rows x 32 s8 = 20480 B
#define BROW 656            // B row stride bytes (640 data + 16 pad; /4 mod 32 == 4 -> conflict-free)
#define BQ_B 16416          // per-q B bytes (25*656=16400, 16-align)
#define AT1S 632            // g_att1 floats per q (625 + pad)

// output layout: [ftrain_out 400000][ftest_out 32000000][am 50000][cls 10000]
#define OFT_TE  400000
#define OFT_AM  32400000
#define OFT_CLS 32450000

// ---------------- device scratch ----------------
__device__ __align__(16) unsigned char g_Ah[NKC * CHUNK_BYTES]; // swizzled s8 A image (400KB)
__device__ float g_sa[MPAD];                                    // inv scale per Gram row
__device__ __align__(16) float g_att1[QQ * AT1S];               // att1[q][p*25+s]
__device__ float g_part[200 * SS];                              // partials for final

// ---------------- smem byte offsets (cam_main) ----------------
#define OB_A     0        // 81920: A ring 4x20480; later G fp16 2x32512; later fq1/out1 staging
#define OB_B     81920    // region 64800: B0@0, B1@16416; later fq0/out0 staging (64000)
#define OB_AT1   146720   // 2 x 632 x 4 = 5056
#define OB_ATT   151776   // 2 x 625 x 4 = 5000
#define OB_KN    156776   // 16 x 112 x 4 = 7168
#define OB_W1F   163944   // 125 f
#define OB_W2    164444   // 125 f
#define OB_B1F   164944   // 5 f
#define OB_B2S   164964   // 25 f
#define OB_NINV  165064   // 2 x 25 f
#define OB_TS    165264   // 2 x 25 f
#define OB_SA    165464   // 625 f inv_sa = 2500
#define OB_SB    167964   // 2 x 32 f inv_sb = 256
#define OB_MBAR  168224   // 8 mbarriers x 8B
#define SMEM_BYTES 168288

#define GH_STRIDE 32512

#define AT1I (OB_AT1/4)
#define ATI  (OB_ATT/4)
#define KNI  (OB_KN/4)

__device__ __forceinline__ float warp_sum(float v) {
    #pragma unroll
    for (int o = 16; o; o >>= 1) v += __shfl_xor_sync(0xffffffffu, v, o);
    return v;
}
__device__ __forceinline__ float warp_max(float v) {
    #pragma unroll
    for (int o = 16; o; o >>= 1) v = fmaxf(v, __shfl_xor_sync(0xffffffffu, v, o));
    return v;
}
__device__ __forceinline__ void mbar_init(uint32_t mbar, uint32_t cnt) {
    asm volatile("mbarrier.init.shared.b64 [%0], %1;" :: "r"(mbar), "r"(cnt) : "memory");
}
__device__ __forceinline__ void mbar_expect_tx(uint32_t mbar, uint32_t bytes) {
    asm volatile("mbarrier.arrive.expect_tx.shared.b64 _, [%0], %1;"
                 :: "r"(mbar), "r"(bytes) : "memory");
}
__device__ __forceinline__ void mbar_wait(uint32_t mbar, uint32_t parity) {
    asm volatile(
        "{\n\t.reg .pred P;\n\t"
        "W_%=:\n\t"
        "mbarrier.try_wait.parity.acquire.cta.shared::cta.b64 P, [%0], %1, 0x989680;\n\t"
        "@P bra D_%=;\n\t"
        "bra.uni W_%=;\n\t"
        "D_%=:\n\t}"
        :: "r"(mbar), "r"(parity) : "memory");
}
__device__ __forceinline__ void bulk_ld(uint32_t dst, const void* src, uint32_t bytes,
                                        uint32_t mbar) {
    asm volatile("cp.async.bulk.shared::cluster.global.mbarrier::complete_tx::bytes "
                 "[%0], [%1], %2, [%3];"
                 :: "r"(dst), "l"(src), "r"(bytes), "r"(mbar) : "memory");
}
__device__ __forceinline__ void bulk_st(void* gdst, uint32_t ssrc, uint32_t bytes) {
    asm volatile("cp.async.bulk.global.shared::cta.bulk_group [%0], [%1], %2;"
                 :: "l"(gdst), "r"(ssrc), "r"(bytes) : "memory");
}
#define BULK_COMMIT() asm volatile("cp.async.bulk.commit_group;" ::: "memory")
#define BULK_WAIT0()  asm volatile("cp.async.bulk.wait_group 0;" ::: "memory")
#define FENCE_ASYNC() asm volatile("fence.proxy.async.shared::cta;" ::: "memory")

__device__ __forceinline__ void ldsm_x4(uint32_t& r0, uint32_t& r1, uint32_t& r2, uint32_t& r3,
                                        uint32_t addr) {
    asm volatile("ldmatrix.sync.aligned.m8n8.x4.shared.b16 {%0,%1,%2,%3}, [%4];"
                 : "=r"(r0), "=r"(r1), "=r"(r2), "=r"(r3) : "r"(addr));
}
// int8 mma: s32 accumulators
__device__ __forceinline__ void mma16832s8(int& d0, int& d1, int& d2, int& d3,
                                           uint32_t a0, uint32_t a1, uint32_t a2, uint32_t a3,
                                           uint32_t b0, uint32_t b1) {
    asm volatile("mma.sync.aligned.m16n8k32.row.col.s32.s8.s8.s32 "
                 "{%0,%1,%2,%3}, {%4,%5,%6,%7}, {%8,%9}, {%0,%1,%2,%3};"
                 : "+r"(d0), "+r"(d1), "+r"(d2), "+r"(d3)
                 : "r"(a0), "r"(a1), "r"(a2), "r"(a3), "r"(b0), "r"(b1));
}
__device__ __forceinline__ int8_t quant8(float v) {
    int q = __float2int_rn(v);
    q = max(-127, min(127, q));
    return (int8_t)q;
}

// ---------------- K1: build swizzled s8 A image + row scales ----------------
__global__ void __launch_bounds__(256) cam_prep_A(const float* __restrict__ ftrain) {
    extern __shared__ float sm[];
    float* xs    = sm;                       // 16000 f
    float* inv_s = sm + 16000;               // 25 f
    float* sca   = sm + 16032;               // 25 f (quant scale per row)
    unsigned char* buf = (unsigned char*)sm + 64256;  // 16000 B
    int p = blockIdx.x, tid = threadIdx.x, lane = tid & 31, w = tid >> 5;
    const float4* fp4 = (const float4*)(ftrain + p * TILE);
    float4* xs4 = (float4*)xs;
    for (int i = tid; i < 4000; i += 256) xs4[i] = fp4[i];
    __syncthreads();
    for (int s = w; s < SS; s += 8) {
        float acc = 0.f, mx = 0.f;
        #pragma unroll
        for (int k = 0; k < 20; k++) {
            float v = xs[(lane + 32 * k) * SS + s];
            acc += v * v;
            mx = fmaxf(mx, fabsf(v));
        }
        acc = warp_sum(acc);
        mx  = warp_max(mx);
        if (lane == 0) {
            float iv = 1.f / fmaxf(sqrtf(acc), 1e-12f);
            inv_s[s] = iv;
            float rmax = fmaxf(mx * iv, 1e-20f);   // max |normalized|
            sca[s] = 127.f / rmax;
            g_sa[p * SS + s] = rmax * (1.f / 127.f);
        }
    }
    __syncthreads();
    for (int idx = tid; idx < TILE; idx += 256) {
        int c = idx / SS, s = idx - c * SS;
        int8_t q = quant8(xs[idx] * inv_s[s] * sca[s]);
        int m = p * SS + s;
        int kc = c >> 5, k = c & 31, k16 = k >> 1;
        uint32_t off = (uint32_t)(((((k16 >> 3) ^ ((m >> 2) & 1)) << 4)) + ((k16 & 7) << 1) + (k & 1));
        *(int8_t*)(buf + kc * 800 + s * 32 + off) = q;
    }
    __syncthreads();
    // coalesced: per chunk, 25 rows (800B) at (kc*640 + p*25)*32
    for (int i = tid; i < 1000; i += 256) {
        int kc = i / 50, j = i - kc * 50;
        *(float4*)(g_Ah + (size_t)(kc * MPAD + p * SS) * 32 + j * 16) =
            *(const float4*)(buf + kc * 800 + j * 16);
    }
}

// ---------------- K2: main kernel, 2 q per CTA, bulk-async, INT8 IMMA ----------------
__global__ void __launch_bounds__(512, 1) cam_main(
    const float* __restrict__ ftest,
    const float* __restrict__ conv1_w, const float* __restrict__ conv1_b,
    const float* __restrict__ bn_gamma, const float* __restrict__ bn_beta,
    const float* __restrict__ bn_mean, const float* __restrict__ bn_var,
    const float* __restrict__ conv2_w, const float* __restrict__ conv2_b,
    float* __restrict__ out)
{
    extern __shared__ char smraw[];
    float* smf = (float*)smraw;
    const int tid = threadIdx.x, lane = tid & 31, w = tid >> 5;
    const int h = w >> 3;                 // q index within CTA (0/1)
    const int wl = w & 7;                 // warp within half
    const int q0 = blockIdx.x * 2;
    const int q = q0 + h;
    const uint32_t smb = (uint32_t)__cvta_generic_to_shared(smraw);
    const uint32_t MB = smb + OB_MBAR;

    if (tid == 0) {
        #pragma unroll
        for (int b = 0; b < 8; b++) mbar_init(MB + b * 8, 1);
    }
    for (int i = tid; i < 125; i += 512) {
        int cc = i / 25;
        smf[OB_W1F/4 + i] = conv1_w[i] * bn_gamma[cc] * rsqrtf(bn_var[cc] + 1e-5f);
        smf[OB_W2/4 + i]  = conv2_w[i];
    }
    if (tid < 5) {
        float scv = bn_gamma[tid] * rsqrtf(bn_var[tid] + 1e-5f);
        smf[OB_B1F/4 + tid] = (conv1_b[tid] - bn_mean[tid]) * scv + bn_beta[tid];
    }
    if (tid < 25) smf[OB_B2S/4 + tid] = conv2_b[tid];
    for (int i = tid; i < 625; i += 512) smf[OB_SA/4 + i] = g_sa[i];
    __syncthreads();   // mbarrier init visible

    // ---- setup: stage fq (bulk), norms+quant scales, build s8 B ----
    for (int qi = 0; qi < 2; qi++) {
        if (tid == 0) {
            mbar_expect_tx(MB + (4 + qi) * 8, TILE * 4);
            bulk_ld(smb + OB_A, ftest + (size_t)(q0 + qi) * TILE, TILE * 4, MB + (4 + qi) * 8);
        }
        mbar_wait(MB + (4 + qi) * 8, 0);
        const float* fqs = (const float*)(smraw + OB_A);
        for (int s = w; s < SS; s += 16) {
            float acc = 0.f, mx = 0.f;
            #pragma unroll
            for (int k = 0; k < 20; k++) {
                float v = fqs[(lane + 32 * k) * SS + s];
                acc += v * v;
                mx = fmaxf(mx, fabsf(v));
            }
            acc = warp_sum(acc);
            mx  = warp_max(mx);
            if (lane == 0) {
                float iv = 1.f / fmaxf(sqrtf(acc), 1e-12f);
                smf[OB_NINV/4 + qi * 25 + s] = iv;
                float bmax = fmaxf(mx * iv, 1e-20f);
                smf[OB_SB/4 + qi * 32 + s] = bmax * (1.f / 127.f);   // inv_sb
            }
        }
        __syncthreads();
        // quantize B: row s = 640 s8 linear (stride BROW), 4 c per thread
        for (int i = tid; i < 4000; i += 512) {
            int s = i / 160, c4 = (i - s * 160) * 4;
            float fsc = smf[OB_NINV/4 + qi * 25 + s] * (127.f / (smf[OB_SB/4 + qi * 32 + s] * 127.f));
            // fsc = inv_norm * sb ; sb = 1/inv_sb
            uchar4 pk;
            pk.x = (unsigned char)quant8(fqs[(c4 + 0) * SS + s] * fsc);
            pk.y = (unsigned char)quant8(fqs[(c4 + 1) * SS + s] * fsc);
            pk.z = (unsigned char)quant8(fqs[(c4 + 2) * SS + s] * fsc);
            pk.w = (unsigned char)quant8(fqs[(c4 + 3) * SS + s] * fsc);
            *(uchar4*)(smraw + OB_B + qi * BQ_B + s * BROW + c4) = pk;
        }
        __syncthreads();
    }

    // ---- start A stream (bulk ring, prefetch 3) ----
    if (tid == 0) {
        #pragma unroll
        for (int pc = 0; pc < 3; pc++) {
            mbar_expect_tx(MB + pc * 8, CHUNK_BYTES);
            bulk_ld(smb + OB_A + pc * CHUNK_BYTES, g_Ah + (size_t)pc * CHUNK_BYTES,
                    CHUNK_BYTES, MB + pc * 8);
        }
    }

    // ---- GEMM: each warp 5 m-tiles x 4 n-tiles, s32 accumulators ----
    int acc[5][4][4];
    #pragma unroll
    for (int t = 0; t < 5; t++)
        #pragma unroll
        for (int n = 0; n < 4; n++)
            #pragma unroll
            for (int e = 0; e < 4; e++) acc[t][n][e] = 0;

    const int nrow = lane >> 2;
    const int kq   = lane & 3;
    const uint32_t bqbase = OB_B + h * BQ_B;

    for (int i = 0; i < NKC; i++) {
        __syncthreads();                          // prior reads of slot (i+3)&3 done
        if (tid == 0 && i + 3 < NKC) {
            int b = (i + 3) & 3;
            mbar_expect_tx(MB + b * 8, CHUNK_BYTES);
            bulk_ld(smb + OB_A + b * CHUNK_BYTES, g_Ah + (size_t)(i + 3) * CHUNK_BYTES,
                    CHUNK_BYTES, MB + b * 8);
        }
        mbar_wait(MB + (i & 3) * 8, (i >> 2) & 1);
        const uint32_t abase = smb + OB_A + (i & 3) * CHUNK_BYTES;

        uint32_t bf[4][2];
        #pragma unroll
        for (int nt = 0; nt < 3; nt++) {
            int n = nt * 8 + nrow;
            uint32_t bidx = bqbase + (uint32_t)(n * BROW + i * 32 + kq * 4);
            bf[nt][0] = *(const uint32_t*)(smraw + bidx);
            bf[nt][1] = *(const uint32_t*)(smraw + bidx + 16);
        }
        if (nrow == 0) {   // only n=24 valid in last n-tile
            uint32_t bidx = bqbase + (uint32_t)(24 * BROW + i * 32 + kq * 4);
            bf[3][0] = *(const uint32_t*)(smraw + bidx);
            bf[3][1] = *(const uint32_t*)(smraw + bidx + 16);
        } else {
            bf[3][0] = 0u; bf[3][1] = 0u;
        }

        #pragma unroll
        for (int j = 0; j < 5; j++) {
            int mt = wl + 8 * j;
            int m = mt * 16 + (lane & 15);
            uint32_t addr = abase + m * 32 + ((((lane >> 4) ^ (m >> 2)) & 1) << 4);
            uint32_t a0, a1, a2, a3;
            ldsm_x4(a0, a1, a2, a3, addr);
            #pragma unroll
            for (int nt = 0; nt < 4; nt++)
                mma16832s8(acc[j][nt][0], acc[j][nt][1], acc[j][nt][2], acc[j][nt][3],
                           a0, a1, a2, a3, bf[nt][0], bf[nt][1]);
        }
    }
    __syncthreads();   // ring + B operands dead

    // prefetch raw fq0 for output into B region (overlaps epilogue)
    if (tid == 0) {
        mbar_expect_tx(MB + 6 * 8, TILE * 4);
        bulk_ld(smb + OB_B, ftest + (size_t)q0 * TILE, TILE * 4, MB + 6 * 8);
    }

    // ---- store G (dequant s32 -> fp16, per-half buffer in dead A region) ----
    {
        __half* gh = (__half*)(smraw + OB_A + h * GH_STRIDE);
        const float* isa = smf + OB_SA/4;
        const float* isb = smf + OB_SB/4 + h * 32;
        #pragma unroll
        for (int j = 0; j < 5; j++) {
            int mt = wl + 8 * j;
            int r0 = mt * 16 + (lane >> 2);
            int r1 = r0 + 8;
            float sr0 = (r0 < 625) ? isa[r0] : 0.f;
            float sr1 = (r1 < 625) ? isa[r1] : 0.f;
            #pragma unroll
            for (int nt = 0; nt < 4; nt++) {
                int c = nt * 8 + (lane & 3) * 2;
                if (c + 1 < 25) {
                    float sc0 = isb[c], sc1 = isb[c + 1];
                    if (r0 < 625)
                        *(__half2*)(gh + r0 * 26 + c) =
                            __floats2half2_rn((float)acc[j][nt][0] * sr0 * sc0,
                                              (float)acc[j][nt][1] * sr0 * sc1);
                    if (r1 < 625)
                        *(__half2*)(gh + r1 * 26 + c) =
                            __floats2half2_rn((float)acc[j][nt][2] * sr1 * sc0,
                                              (float)acc[j][nt][3] * sr1 * sc1);
                } else if (c < 25) {
                    float sc0 = isb[c];
                    if (r0 < 625) gh[r0 * 26 + c] = __float2half_rn((float)acc[j][nt][0] * sr0 * sc0);
                    if (r1 < 625) gh[r1 * 26 + c] = __float2half_rn((float)acc[j][nt][2] * sr1 * sc0);
                }
            }
        }
    }
    asm volatile("bar.sync %0, 256;" :: "r"(h + 1) : "memory");

    // ---- per-p epilogue (halves parallel) ----
    {
        const __half* gh = (const __half*)(smraw + OB_A + h * GH_STRIDE);
        for (int p = wl; p < PP; p += 8) {
            float* kn = smf + KNI + w * 112;
            if (lane < 25) {
                float a1 = 0.f, a2 = 0.f;
                int rowb = (p * 25 + lane) * 26;
                int colb = p * 25 * 26 + lane;
                #pragma unroll
                for (int j = 0; j < 25; j++) {
                    a1 += __half2float(gh[rowb + j]);
                    a2 += __half2float(gh[colb + j * 26]);
                }
                kn[lane]      = a1 * (1.f / 25.f);   // g1
                kn[25 + lane] = a2 * (1.f / 25.f);   // g2
            }
            __syncwarp();
            if (lane < 5) {
                float a = smf[OB_B1F/4 + lane];
                #pragma unroll
                for (int j = 0; j < 25; j++) a += kn[j] * smf[OB_W1F/4 + lane * 25 + j];
                kn[50 + lane] = fmaxf(a, 0.f);
            } else if (lane >= 8 && lane < 13) {
                int ii = lane - 8;
                float a = smf[OB_B1F/4 + ii];
                #pragma unroll
                for (int j = 0; j < 25; j++) a += kn[25 + j] * smf[OB_W1F/4 + ii * 25 + j];
                kn[55 + ii] = fmaxf(a, 0.f);
            }
            __syncwarp();
            if (lane < 25) {
                float a1 = smf[OB_B2S/4 + lane], a2 = a1;
                #pragma unroll
                for (int ii = 0; ii < 5; ii++) {
                    float wv = smf[OB_W2/4 + lane * 5 + ii];
                    a1 += kn[50 + ii] * wv;
                    a2 += kn[55 + ii] * wv;
                }
                kn[60 + lane] = fmaxf(a1, 0.f);  // k1
                kn[85 + lane] = fmaxf(a2, 0.f);  // k2
            }
            __syncwarp();
            if (lane < 25) {
                float att1 = 0.f, attt = 0.f;
                int colb = p * 25 * 26 + lane;
                int rowb = (p * 25 + lane) * 26;
                #pragma unroll
                for (int j = 0; j < 25; j++) {
                    att1 += kn[60 + j] * __half2float(gh[colb + j * 26]);
                    attt += __half2float(gh[rowb + j]) * kn[85 + j];
                }
                smf[AT1I + h * AT1S + p * 25 + lane] = att1;
                smf[ATI + h * 625 + p * 25 + lane]   = attt;
            }
        }
    }
    __syncthreads();   // both halves done with G

    // prefetch raw fq1 for output into A region
    if (tid == 0) {
        mbar_expect_tx(MB + 7 * 8, TILE * 4);
        bulk_ld(smb + OB_A, ftest + (size_t)(q0 + 1) * TILE, TILE * 4, MB + 7 * 8);
    }

    // ---- softmaxes (per half) ----
    if (wl == 0) {
        float val = 0.f;
        if (lane < 25) {
            #pragma unroll
            for (int j = 0; j < 25; j++) val += smf[ATI + h * 625 + j * 25 + lane];
            val *= (1.f / 25.f);
        }
        float m = (lane < 25) ? val : -1e30f;
        #pragma unroll
        for (int o = 16; o; o >>= 1) m = fmaxf(m, __shfl_xor_sync(0xffffffffu, m, o));
        float e = (lane < 25) ? expf(val - m) : 0.f;
        float ssum = e;
        #pragma unroll
        for (int o = 16; o; o >>= 1) ssum += __shfl_xor_sync(0xffffffffu, ssum, o);
        float a = e / ssum;
        if (lane < 25) {
            out[OFT_AM + q * SS + lane] = a;
            smf[OB_TS/4 + h * 25 + lane] = a + 1.f;
        }
    } else if (wl == 1) {
        float rs = 0.f;
        if (lane < 25) {
            #pragma unroll
            for (int j = 0; j < 25; j++) rs += smf[ATI + h * 625 + lane * 25 + j];
        }
        int g = (lane < 5) ? lane : 4;
        float cg = 0.f;
        #pragma unroll
        for (int i = 0; i < 5; i++) cg += __shfl_sync(0xffffffffu, rs, g * 5 + i);
        cg *= (1.f / 125.f);
        float m = (lane < 5) ? cg : -1e30f;
        #pragma unroll
        for (int o = 4; o; o >>= 1) m = fmaxf(m, __shfl_xor_sync(0xffffffffu, m, o));
        float e = (lane < 5) ? expf(cg - m) : 0.f;
        float ssum = e;
        #pragma unroll
        for (int o = 4; o; o >>= 1) ssum += __shfl_xor_sync(0xffffffffu, ssum, o);
        if (lane < 5) out[OFT_CLS + q * 5 + lane] = e / ssum;
    }
    asm volatile("bar.sync %0, 256;" :: "r"(h + 1) : "memory");  // TS[h] ready

    // ---- output: half h scales its fq in smem, bulk-stores out + att1 ----
    {
        const uint32_t stage_off = (h == 0) ? OB_B : OB_A;
        mbar_wait(MB + (6 + h) * 8, 0);
        float4* st4 = (float4*)(smraw + stage_off);
        const int t2 = tid & 255;
        for (int i = t2; i < 4000; i += 256) {
            float4 b = st4[i];
            int s = (i * 4) % 25;
            b.x *= smf[OB_TS/4 + h * 25 + s]; s = (s == 24) ? 0 : s + 1;
            b.y *= smf[OB_TS/4 + h * 25 + s]; s = (s == 24) ? 0 : s + 1;
            b.z *= smf[OB_TS/4 + h * 25 + s]; s = (s == 24) ? 0 : s + 1;
            b.w *= smf[OB_TS/4 + h * 25 + s];
            st4[i] = b;
        }
        asm volatile("bar.sync %0, 256;" :: "r"(h + 1) : "memory");
        if (t2 == 0) {
            FENCE_ASYNC();
            bulk_st(out + OFT_TE + (size_t)q * TILE, smb + stage_off, TILE * 4);
            bulk_st(g_att1 + (size_t)q * AT1S, smb + OB_AT1 + h * (AT1S * 4), AT1S * 4);
            BULK_COMMIT();
            BULK_WAIT0();
        }
    }
    __syncthreads();   // keep smem alive until bulk stores complete
}

// ---------------- K3a: partial reduce of att1 over q slices ----------------
__global__ void __launch_bounds__(128) cam_final1() {
    __shared__ float red[125];
    int p = blockIdx.x >> 3, sl = blockIdx.x & 7;
    int tid = threadIdx.x;
    if (tid < 125) {
        int s = tid % 25, grp = tid / 25;
        const float* base = g_att1 + p * 25 + s;
        float acc = 0.f;
        for (int qq = sl * 250 + grp; qq < (sl + 1) * 250; qq += 5)
            acc += base[(size_t)qq * AT1S];
        red[tid] = acc;
    }
    __syncthreads();
    if (tid < 25) {
        float v = red[tid] + red[25 + tid] + red[50 + tid] + red[75 + tid] + red[100 + tid];
        g_part[blockIdx.x * 25 + tid] = v;
    }
}

// ---------------- K3b: combine, softmax, ftrain_out ----------------
__global__ void __launch_bounds__(256) cam_final2(const float* __restrict__ ftrain,
                                                  float* __restrict__ out) {
    __shared__ float att_s[SS];
    int p = blockIdx.x, tid = threadIdx.x, lane = tid & 31, w = tid >> 5;
    if (w == 0) {
        float val = 0.f;
        if (lane < 25) {
            #pragma unroll
            for (int k = 0; k < 8; k++) val += g_part[(p * 8 + k) * 25 + lane];
            val *= (1.f / (float)QQ);
        }
        float m = (lane < 25) ? val : -1e30f;
        #pragma unroll
        for (int o = 16; o; o >>= 1) m = fmaxf(m, __shfl_xor_sync(0xffffffffu, m, o));
        float e = (lane < 25) ? expf(val - m) : 0.f;
        float ssum = e;
        #pragma unroll
        for (int o = 16; o; o >>= 1) ssum += __shfl_xor_sync(0xffffffffu, ssum, o);
        if (lane < 25) att_s[lane] = e / ssum + 1.f;
    }
    __syncthreads();
    const float4* fp4 = (const float4*)(ftrain + p * TILE);
    float4* outp = (float4*)(out + (size_t)p * TILE);
    for (int i = tid; i < 4000; i += 256) {
        float4 b = fp4[i];
        int s = (i * 4) % 25;
        float4 o;
        o.x = b.x * att_s[s]; s = (s == 24) ? 0 : s + 1;
        o.y = b.y * att_s[s]; s = (s == 24) ? 0 : s + 1;
        o.z = b.z * att_s[s]; s = (s == 24) ? 0 : s + 1;
        o.w = b.w * att_s[s];
        outp[i] = o;
    }
}

// ---------------- launch ----------------
extern "C" void kernel_launch(void* const* d_in, const int* in_sizes, int n_in,
                              void* d_out, int out_size) {
    const float* ftrain  = (const float*)d_in[0];
    const float* ftest   = (const float*)d_in[1];
    const float* conv1_w = (const float*)d_in[6];
    const float* conv1_b = (const float*)d_in[7];
    const float* bn_gamma= (const float*)d_in[8];
    const float* bn_beta = (const float*)d_in[9];
    const float* bn_mean = (const float*)d_in[10];
    const float* bn_var  = (const float*)d_in[11];
    const float* conv2_w = (const float*)d_in[12];
    const float* conv2_b = (const float*)d_in[13];
    float* out = (float*)d_out;

    const int prepA_smem = 64256 + 16000;
    cudaFuncSetAttribute(cam_prep_A, cudaFuncAttributeMaxDynamicSharedMemorySize, prepA_smem);
    cudaFuncSetAttribute(cam_main,   cudaFuncAttributeMaxDynamicSharedMemorySize, SMEM_BYTES);

    cam_prep_A<<<PP, 256, prepA_smem>>>(ftrain);
    cam_main<<<QQ / 2, 512, SMEM_BYTES>>>(ftest, conv1_w, conv1_b, bn_gamma, bn_beta,
                                          bn_mean, bn_var, conv2_w, conv2_b, out);
    cam_final1<<<200, 128>>>();
    cam_final2<<<PP, 256>>>(ftrain, out);
}

// round 12
// speedup vs baseline: 2.7221x; 2.7221x over previous
#include <cuda_runtime.h>
#include <cuda_fp16.h>
#include <math.h>
#include <stdint.h>

#define PP   25
#define QQ   2000
#define CC   640
#define SS   25
#define TILE 16000

#define MPAD 640
#define NKC  40
#define CHUNK_BYTES (MPAD * 32)   // 20480
#define RSTRIDE 21600             // ring slot stride (3 slots = 64800 >= 64000 staging)
#define SLOT  32512               // per-q B / G slot bytes
#define AT1S  632

#define OFT_TE  400000
#define OFT_AM  32400000
#define OFT_CLS 32450000

__device__ __align__(16) unsigned char g_Ah[NKC * CHUNK_BYTES];
__device__ __align__(16) float g_att1[QQ * AT1S];
__device__ float g_part[200 * SS];

// ---------------- smem layout (cam_main) ----------------
#define OB_A     0         // 64800: A ring 3x21600; also fq staging during setup
#define OB_B     64800     // 130048: B slots q*SLOT -> later G slots -> later output staging
#define OB_ZROW  194848    // 1312 B zero row
#define OB_AT1   196160    // 4 x 632 x 4
#define OB_ATT   206272    // 4 x 625 x 4
#define OB_KN    216272    // 16 x 112 x 4
#define OB_W1F   223440
#define OB_W2    223940
#define OB_B1F   224440
#define OB_B2S   224460
#define OB_NINV  224560    // 4 x 25 f
#define OB_TS    224960    // 4 x 25 f
#define OB_MBAR  225360    // 8 mbarriers
#define SMEM_BYTES 225440

#define AT1I (OB_AT1/4)
#define ATI  (OB_ATT/4)
#define KNI  (OB_KN/4)
#define ST0  (OB_B)
#define ST1  (OB_B + 65024)

__device__ __forceinline__ float warp_sum(float v) {
    #pragma unroll
    for (int o = 16; o; o >>= 1) v += __shfl_xor_sync(0xffffffffu, v, o);
    return v;
}
__device__ __forceinline__ void mbar_init(uint32_t mbar, uint32_t cnt) {
    asm volatile("mbarrier.init.shared.b64 [%0], %1;" :: "r"(mbar), "r"(cnt) : "memory");
}
__device__ __forceinline__ void mbar_expect_tx(uint32_t mbar, uint32_t bytes) {
    asm volatile("mbarrier.arrive.expect_tx.shared.b64 _, [%0], %1;"
                 :: "r"(mbar), "r"(bytes) : "memory");
}
__device__ __forceinline__ void mbar_wait(uint32_t mbar, uint32_t parity) {
    asm volatile(
        "{\n\t.reg .pred P;\n\t"
        "W_%=:\n\t"
        "mbarrier.try_wait.parity.acquire.cta.shared::cta.b64 P, [%0], %1, 0x989680;\n\t"
        "@P bra D_%=;\n\t"
        "bra.uni W_%=;\n\t"
        "D_%=:\n\t}"
        :: "r"(mbar), "r"(parity) : "memory");
}
__device__ __forceinline__ void bulk_ld(uint32_t dst, const void* src, uint32_t bytes,
                                        uint32_t mbar) {
    asm volatile("cp.async.bulk.shared::cluster.global.mbarrier::complete_tx::bytes "
                 "[%0], [%1], %2, [%3];"
                 :: "r"(dst), "l"(src), "r"(bytes), "r"(mbar) : "memory");
}
__device__ __forceinline__ void bulk_st(void* gdst, uint32_t ssrc, uint32_t bytes) {
    asm volatile("cp.async.bulk.global.shared::cta.bulk_group [%0], [%1], %2;"
                 :: "l"(gdst), "r"(ssrc), "r"(bytes) : "memory");
}
#define BULK_COMMIT() asm volatile("cp.async.bulk.commit_group;" ::: "memory")
#define BULK_WAIT0()  asm volatile("cp.async.bulk.wait_group 0;" ::: "memory")
#define FENCE_ASYNC() asm volatile("fence.proxy.async.shared::cta;" ::: "memory")

__device__ __forceinline__ void ldsm_x4(uint32_t& r0, uint32_t& r1, uint32_t& r2, uint32_t& r3,
                                        uint32_t addr) {
    asm volatile("ldmatrix.sync.aligned.m8n8.x4.shared.b16 {%0,%1,%2,%3}, [%4];"
                 : "=r"(r0), "=r"(r1), "=r"(r2), "=r"(r3) : "r"(addr));
}
__device__ __forceinline__ void mma16816h(uint32_t& d0, uint32_t& d1,
                                          uint32_t a0, uint32_t a1, uint32_t a2, uint32_t a3,
                                          uint32_t b0, uint32_t b1) {
    asm volatile("mma.sync.aligned.m16n8k16.row.col.f16.f16.f16.f16 "
                 "{%0,%1}, {%2,%3,%4,%5}, {%6,%7}, {%0,%1};"
                 : "+r"(d0), "+r"(d1)
                 : "r"(a0), "r"(a1), "r"(a2), "r"(a3), "r"(b0), "r"(b1));
}

// ---------------- K1: build swizzled fp16 A image ----------------
__global__ void __launch_bounds__(256) cam_prep_A(const float* __restrict__ ftrain) {
    extern __shared__ float sm[];
    float* xs    = sm;
    float* inv_s = sm + 16000;
    unsigned char* buf = (unsigned char*)sm + 64128;  // 32000 B
    int p = blockIdx.x, tid = threadIdx.x, lane = tid & 31, w = tid >> 5;
    const float4* fp4 = (const float4*)(ftrain + p * TILE);
    float4* xs4 = (float4*)xs;
    for (int i = tid; i < 4000; i += 256) xs4[i] = fp4[i];
    __syncthreads();
    for (int s = w; s < SS; s += 8) {
        float acc = 0.f;
        #pragma unroll
        for (int k = 0; k < 20; k++) { float v = xs[(lane + 32 * k) * SS + s]; acc += v * v; }
        acc = warp_sum(acc);
        if (lane == 0) inv_s[s] = 1.f / fmaxf(sqrtf(acc), 1e-12f);
    }
    __syncthreads();
    for (int idx = tid; idx < TILE; idx += 256) {
        int c = idx / SS, s = idx - c * SS;
        __half v = __float2half_rn(xs[idx] * inv_s[s]);
        int m = p * SS + s;
        int kc = c >> 4, k = c & 15;
        uint32_t off = (uint32_t)((((k >> 3) ^ ((m >> 2) & 1)) << 4) + ((k & 7) << 1));
        *(__half*)(buf + kc * 800 + s * 32 + off) = v;
    }
    __syncthreads();
    for (int i = tid; i < 2000; i += 256) {
        int kc = i / 50, j = i - kc * 50;
        *(float4*)(g_Ah + (size_t)(kc * MPAD + p * SS) * 32 + j * 16) =
            *(const float4*)(buf + kc * 800 + j * 16);
    }
}

// ---------------- K2: main kernel, 4 q per CTA, N=104 packed GEMM ----------------
__global__ void __launch_bounds__(512, 1) cam_main(
    const float* __restrict__ ftest,
    const float* __restrict__ conv1_w, const float* __restrict__ conv1_b,
    const float* __restrict__ bn_gamma, const float* __restrict__ bn_beta,
    const float* __restrict__ bn_mean, const float* __restrict__ bn_var,
    const float* __restrict__ conv2_w, const float* __restrict__ conv2_b,
    float* __restrict__ out)
{
    extern __shared__ char smraw[];
    float* smf = (float*)smraw;
    const int tid = threadIdx.x, lane = tid & 31, w = tid >> 5;
    const int q0 = blockIdx.x * 4;
    const uint32_t smb = (uint32_t)__cvta_generic_to_shared(smraw);
    const uint32_t MB = smb + OB_MBAR;

    if (tid == 0) {
        #pragma unroll
        for (int b = 0; b < 8; b++) mbar_init(MB + b * 8, 1);
    }
    for (int i = tid; i < 125; i += 512) {
        int cc = i / 25;
        smf[OB_W1F/4 + i] = conv1_w[i] * bn_gamma[cc] * rsqrtf(bn_var[cc] + 1e-5f);
        smf[OB_W2/4 + i]  = conv2_w[i];
    }
    if (tid < 5) {
        float scv = bn_gamma[tid] * rsqrtf(bn_var[tid] + 1e-5f);
        smf[OB_B1F/4 + tid] = (conv1_b[tid] - bn_mean[tid]) * scv + bn_beta[tid];
    }
    if (tid < 25) smf[OB_B2S/4 + tid] = conv2_b[tid];
    for (int i = tid; i < 328; i += 512) *(uint32_t*)(smraw + OB_ZROW + i * 4) = 0u;
    __syncthreads();

    // ---- setup: stage fq (bulk into ring region), norms, build B (4 q) ----
    for (int qi = 0; qi < 4; qi++) {
        if (tid == 0) {
            mbar_expect_tx(MB + 3 * 8, TILE * 4);
            bulk_ld(smb + OB_A, ftest + (size_t)(q0 + qi) * TILE, TILE * 4, MB + 3 * 8);
        }
        mbar_wait(MB + 3 * 8, qi & 1);
        const float* fqs = (const float*)(smraw + OB_A);
        for (int s = w; s < SS; s += 16) {
            float acc = 0.f;
            #pragma unroll
            for (int k = 0; k < 20; k++) { float v = fqs[(lane + 32 * k) * SS + s]; acc += v * v; }
            acc = warp_sum(acc);
            if (lane == 0) smf[OB_NINV/4 + qi * 25 + s] = 1.f / fmaxf(sqrtf(acc), 1e-12f);
        }
        __syncthreads();
        for (int i = tid; i < 8000; i += 512) {
            int s = i / 320, c2 = i - s * 320;
            float iv = smf[OB_NINV/4 + qi * 25 + s];
            __half2 v = __floats2half2_rn(fqs[(2 * c2) * SS + s] * iv,
                                          fqs[(2 * c2 + 1) * SS + s] * iv);
            *(__half2*)(smraw + OB_B + qi * SLOT + (s * 648 + 2 * c2) * 2) = v;
        }
        __syncthreads();
    }

    // ---- start A stream (ring 3, prefetch 2) ----
    if (tid == 0) {
        #pragma unroll
        for (int pc = 0; pc < 2; pc++) {
            mbar_expect_tx(MB + pc * 8, CHUNK_BYTES);
            bulk_ld(smb + OB_A + pc * RSTRIDE, g_Ah + (size_t)pc * CHUNK_BYTES,
                    CHUNK_BYTES, MB + pc * 8);
        }
    }

    // per-lane B base addresses for 13 n-tiles (rows 0..103; pad rows -> zero row)
    uint32_t bbase[13];
    #pragma unroll
    for (int nt = 0; nt < 13; nt++) {
        int rn = nt * 8 + (lane >> 2);
        if (rn < 100) {
            int qq = rn / 25, r = rn - qq * 25;
            bbase[nt] = (uint32_t)(OB_B + qq * SLOT + r * 1296 + (lane & 3) * 4);
        } else {
            bbase[nt] = (uint32_t)(OB_ZROW + (lane & 3) * 4);
        }
    }

    // m-tile assignment: warps 0-7: {w, w+16, w+32}; warps 8-15: {w, w+16}
    const int nmt = (w < 8) ? 3 : 2;
    uint32_t hacc0[3][13], hacc1[3][13];
    #pragma unroll
    for (int j = 0; j < 3; j++)
        #pragma unroll
        for (int nt = 0; nt < 13; nt++) { hacc0[j][nt] = 0u; hacc1[j][nt] = 0u; }

    for (int i = 0; i < NKC; i++) {
        __syncthreads();
        if (tid == 0 && i + 2 < NKC) {
            int b = (i + 2) % 3;
            mbar_expect_tx(MB + b * 8, CHUNK_BYTES);
            bulk_ld(smb + OB_A + b * RSTRIDE, g_Ah + (size_t)(i + 2) * CHUNK_BYTES,
                    CHUNK_BYTES, MB + b * 8);
        }
        mbar_wait(MB + (i % 3) * 8, (uint32_t)((i / 3) & 1));
        const uint32_t abase = smb + OB_A + (i % 3) * RSTRIDE;

        // load all A fragments for this chunk (<=3 m-tiles)
        uint32_t af[3][4];
        #pragma unroll
        for (int j = 0; j < 3; j++) {
            if (j >= nmt) break;
            int m = (w + 16 * j) * 16 + (lane & 15);
            uint32_t addr = abase + m * 32 + ((((lane >> 4) ^ (m >> 2)) & 1) << 4);
            ldsm_x4(af[j][0], af[j][1], af[j][2], af[j][3], addr);
        }
        const uint32_t koff = (uint32_t)(i * 32);
        #pragma unroll
        for (int nt = 0; nt < 13; nt++) {
            uint32_t b0 = *(const uint32_t*)(smraw + bbase[nt] + koff);
            uint32_t b1 = *(const uint32_t*)(smraw + bbase[nt] + koff + 16);
            mma16816h(hacc0[0][nt], hacc1[0][nt], af[0][0], af[0][1], af[0][2], af[0][3], b0, b1);
            mma16816h(hacc0[1][nt], hacc1[1][nt], af[1][0], af[1][1], af[1][2], af[1][3], b0, b1);
            if (nmt == 3)
                mma16816h(hacc0[2][nt], hacc1[2][nt], af[2][0], af[2][1], af[2][2], af[2][3], b0, b1);
        }
    }
    __syncthreads();   // all GEMM reads done; B region becomes G region

    // ---- store G (fp16, 4 q slots over the dead B region) ----
    #pragma unroll
    for (int j = 0; j < 3; j++) {
        if (j >= nmt) break;
        int r0 = (w + 16 * j) * 16 + (lane >> 2);
        int r1 = r0 + 8;
        #pragma unroll
        for (int nt = 0; nt < 13; nt++) {
            int cg = nt * 8 + (lane & 3) * 2;
            __half2 v0 = *reinterpret_cast<__half2*>(&hacc0[j][nt]);
            __half2 v1 = *reinterpret_cast<__half2*>(&hacc1[j][nt]);
            #pragma unroll
            for (int e = 0; e < 2; e++) {
                int cge = cg + e;
                if (cge < 100) {
                    int qq = cge / 25, c = cge - qq * 25;
                    __half* gq = (__half*)(smraw + OB_B + qq * SLOT);
                    __half h0 = (e == 0) ? __low2half(v0) : __high2half(v0);
                    __half h1 = (e == 0) ? __low2half(v1) : __high2half(v1);
                    if (r0 < 625) gq[r0 * 26 + c] = h0;
                    if (r1 < 625) gq[r1 * 26 + c] = h1;
                }
            }
        }
    }
    __syncthreads();

    // ---- per-(q,p) epilogue: 100 tasks over 16 warps ----
    for (int task = w; task < 100; task += 16) {
        int qq = task / 25, p = task - qq * 25;
        const __half* gh = (const __half*)(smraw + OB_B + qq * SLOT);
        float* kn = smf + KNI + w * 112;
        if (lane < 25) {
            float a1 = 0.f, a2 = 0.f;
            int rowb = (p * 25 + lane) * 26;
            int colb = p * 25 * 26 + lane;
            #pragma unroll
            for (int j = 0; j < 25; j++) {
                a1 += __half2float(gh[rowb + j]);
                a2 += __half2float(gh[colb + j * 26]);
            }
            kn[lane]      = a1 * (1.f / 25.f);
            kn[25 + lane] = a2 * (1.f / 25.f);
        }
        __syncwarp();
        if (lane < 5) {
            float a = smf[OB_B1F/4 + lane];
            #pragma unroll
            for (int j = 0; j < 25; j++) a += kn[j] * smf[OB_W1F/4 + lane * 25 + j];
            kn[50 + lane] = fmaxf(a, 0.f);
        } else if (lane >= 8 && lane < 13) {
            int ii = lane - 8;
            float a = smf[OB_B1F/4 + ii];
            #pragma unroll
            for (int j = 0; j < 25; j++) a += kn[25 + j] * smf[OB_W1F/4 + ii * 25 + j];
            kn[55 + ii] = fmaxf(a, 0.f);
        }
        __syncwarp();
        if (lane < 25) {
            float a1 = smf[OB_B2S/4 + lane], a2 = a1;
            #pragma unroll
            for (int ii = 0; ii < 5; ii++) {
                float wv = smf[OB_W2/4 + lane * 5 + ii];
                a1 += kn[50 + ii] * wv;
                a2 += kn[55 + ii] * wv;
            }
            kn[60 + lane] = fmaxf(a1, 0.f);
            kn[85 + lane] = fmaxf(a2, 0.f);
        }
        __syncwarp();
        if (lane < 25) {
            float att1 = 0.f, attt = 0.f;
            int colb = p * 25 * 26 + lane;
            int rowb = (p * 25 + lane) * 26;
            #pragma unroll
            for (int j = 0; j < 25; j++) {
                att1 += kn[60 + j] * __half2float(gh[colb + j * 26]);
                attt += __half2float(gh[rowb + j]) * kn[85 + j];
            }
            smf[AT1I + qq * AT1S + p * 25 + lane] = att1;
            smf[ATI + qq * 625 + p * 25 + lane]   = attt;
        }
    }
    __syncthreads();   // epilogue done; G dead

    // prefetch raw fq0, fq1 for output (into dead G region)
    if (tid == 0) {
        mbar_expect_tx(MB + 4 * 8, TILE * 4);
        bulk_ld(smb + ST0, ftest + (size_t)q0 * TILE, TILE * 4, MB + 4 * 8);
        mbar_expect_tx(MB + 5 * 8, TILE * 4);
        bulk_ld(smb + ST1, ftest + (size_t)(q0 + 1) * TILE, TILE * 4, MB + 5 * 8);
    }

    // ---- softmaxes: warps 0-7: q = w>>1, role = w&1 ----
    if (w < 8) {
        int qq = w >> 1;
        if ((w & 1) == 0) {
            float val = 0.f;
            if (lane < 25) {
                #pragma unroll
                for (int j = 0; j < 25; j++) val += smf[ATI + qq * 625 + j * 25 + lane];
                val *= (1.f / 25.f);
            }
            float m = (lane < 25) ? val : -1e30f;
            #pragma unroll
            for (int o = 16; o; o >>= 1) m = fmaxf(m, __shfl_xor_sync(0xffffffffu, m, o));
            float e = (lane < 25) ? expf(val - m) : 0.f;
            float ssum = e;
            #pragma unroll
            for (int o = 16; o; o >>= 1) ssum += __shfl_xor_sync(0xffffffffu, ssum, o);
            float a = e / ssum;
            if (lane < 25) {
                out[OFT_AM + (q0 + qq) * SS + lane] = a;
                smf[OB_TS/4 + qq * 25 + lane] = a + 1.f;
            }
        } else {
            float rs = 0.f;
            if (lane < 25) {
                #pragma unroll
                for (int j = 0; j < 25; j++) rs += smf[ATI + qq * 625 + lane * 25 + j];
            }
            int g = (lane < 5) ? lane : 4;
            float cg = 0.f;
            #pragma unroll
            for (int i = 0; i < 5; i++) cg += __shfl_sync(0xffffffffu, rs, g * 5 + i);
            cg *= (1.f / 125.f);
            float m = (lane < 5) ? cg : -1e30f;
            #pragma unroll
            for (int o = 4; o; o >>= 1) m = fmaxf(m, __shfl_xor_sync(0xffffffffu, m, o));
            float e = (lane < 5) ? expf(cg - m) : 0.f;
            float ssum = e;
            #pragma unroll
            for (int o = 4; o; o >>= 1) ssum += __shfl_xor_sync(0xffffffffu, ssum, o);
            if (lane < 5) out[OFT_CLS + (q0 + qq) * 5 + lane] = e / ssum;
        }
    }
    __syncthreads();   // TS ready

    // ---- output: 2 rounds x 2 q (halves), bulk staged ----
    const int h = w >> 3;
    const int t2 = tid & 255;
    #pragma unroll
    for (int r = 0; r < 2; r++) {
        int qq = r * 2 + h;
        mbar_wait(MB + (4 + h) * 8, (uint32_t)r);
        float4* st4 = (float4*)(smraw + (h == 0 ? ST0 : ST1));
        const float* ts = smf + OB_TS/4 + qq * 25;
        for (int i = t2; i < 4000; i += 256) {
            float4 b = st4[i];
            int s = (i * 4) % 25;
            b.x *= ts[s]; s = (s == 24) ? 0 : s + 1;
            b.y *= ts[s]; s = (s == 24) ? 0 : s + 1;
            b.z *= ts[s]; s = (s == 24) ? 0 : s + 1;
            b.w *= ts[s];
            st4[i] = b;
        }
        __syncthreads();
        if (tid == 0) {
            FENCE_ASYNC();
            bulk_st(out + OFT_TE + (size_t)(q0 + r * 2) * TILE, smb + ST0, TILE * 4);
            bulk_st(out + OFT_TE + (size_t)(q0 + r * 2 + 1) * TILE, smb + ST1, TILE * 4);
            bulk_st(g_att1 + (size_t)(q0 + r * 2) * AT1S,
                    smb + OB_AT1 + (r * 2) * (AT1S * 4), AT1S * 4);
            bulk_st(g_att1 + (size_t)(q0 + r * 2 + 1) * AT1S,
                    smb + OB_AT1 + (r * 2 + 1) * (AT1S * 4), AT1S * 4);
            BULK_COMMIT();
            BULK_WAIT0();
            if (r == 0) {
                mbar_expect_tx(MB + 4 * 8, TILE * 4);
                bulk_ld(smb + ST0, ftest + (size_t)(q0 + 2) * TILE, TILE * 4, MB + 4 * 8);
                mbar_expect_tx(MB + 5 * 8, TILE * 4);
                bulk_ld(smb + ST1, ftest + (size_t)(q0 + 3) * TILE, TILE * 4, MB + 5 * 8);
            }
        }
    }
    __syncthreads();
}

// ---------------- K3a: partial reduce of att1 over q slices ----------------
__global__ void __launch_bounds__(128) cam_final1() {
    __shared__ float red[125];
    int p = blockIdx.x >> 3, sl = blockIdx.x & 7;
    int tid = threadIdx.x;
    if (tid < 125) {
        int s = tid % 25, grp = tid / 25;
        const float* base = g_att1 + p * 25 + s;
        float acc = 0.f;
        for (int qq = sl * 250 + grp; qq < (sl + 1) * 250; qq += 5)
            acc += base[(size_t)qq * AT1S];
        red[tid] = acc;
    }
    __syncthreads();
    if (tid < 25) {
        float v = red[tid] + red[25 + tid] + red[50 + tid] + red[75 + tid] + red[100 + tid];
        g_part[blockIdx.x * 25 + tid] = v;
    }
}

// ---------------- K3b: combine, softmax, ftrain_out ----------------
__global__ void __launch_bounds__(256) cam_final2(const float* __restrict__ ftrain,
                                                  float* __restrict__ out) {
    __shared__ float att_s[SS];
    int p = blockIdx.x, tid = threadIdx.x, lane = tid & 31, w = tid >> 5;
    if (w == 0) {
        float val = 0.f;
        if (lane < 25) {
            #pragma unroll
            for (int k = 0; k < 8; k++) val += g_part[(p * 8 + k) * 25 + lane];
            val *= (1.f / (float)QQ);
        }
        float m = (lane < 25) ? val : -1e30f;
        #pragma unroll
        for (int o = 16; o; o >>= 1) m = fmaxf(m, __shfl_xor_sync(0xffffffffu, m, o));
        float e = (lane < 25) ? expf(val - m) : 0.f;
        float ssum = e;
        #pragma unroll
        for (int o = 16; o; o >>= 1) ssum += __shfl_xor_sync(0xffffffffu, ssum, o);
        if (lane < 25) att_s[lane] = e / ssum + 1.f;
    }
    __syncthreads();
    const float4* fp4 = (const float4*)(ftrain + p * TILE);
    float4* outp = (float4*)(out + (size_t)p * TILE);
    for (int i = tid; i < 4000; i += 256) {
        float4 b = fp4[i];
        int s = (i * 4) % 25;
        float4 o;
        o.x = b.x * att_s[s]; s = (s == 24) ? 0 : s + 1;
        o.y = b.y * att_s[s]; s = (s == 24) ? 0 : s + 1;
        o.z = b.z * att_s[s]; s = (s == 24) ? 0 : s + 1;
        o.w = b.w * att_s[s];
        outp[i] = o;
    }
}

// ---------------- launch ----------------
extern "C" void kernel_launch(void* const* d_in, const int* in_sizes, int n_in,
                              void* d_out, int out_size) {
    const float* ftrain  = (const float*)d_in[0];
    const float* ftest   = (const float*)d_in[1];
    const float* conv1_w = (const float*)d_in[6];
    const float* conv1_b = (const float*)d_in[7];
    const float* bn_gamma= (const float*)d_in[8];
    const float* bn_beta = (const float*)d_in[9];
    const float* bn_mean = (const float*)d_in[10];
    const float* bn_var  = (const float*)d_in[11];
    const float* conv2_w = (const float*)d_in[12];
    const float* conv2_b = (const float*)d_in[13];
    float* out = (float*)d_out;

    const int prepA_smem = 64128 + 32000;
    cudaFuncSetAttribute(cam_prep_A, cudaFuncAttributeMaxDynamicSharedMemorySize, prepA_smem);
    cudaFuncSetAttribute(cam_main,   cudaFuncAttributeMaxDynamicSharedMemorySize, SMEM_BYTES);

    cam_prep_A<<<PP, 256, prepA_smem>>>(ftrain);
    cam_main<<<QQ / 4, 512, SMEM_BYTES>>>(ftest, conv1_w, conv1_b, bn_gamma, bn_beta,
                                          bn_mean, bn_var, conv2_w, conv2_b, out);
    cam_final1<<<200, 128>>>();
    cam_final2<<<PP, 256>>>(ftrain, out);
}

// round 13
// speedup vs baseline: 2.7343x; 1.0045x over previous
#include <cuda_runtime.h>
#include <cuda_fp16.h>
#include <math.h>
#include <stdint.h>

#define PP   25
#define QQ   2000
#define CC   640
#define SS   25
#define TILE 16000

#define MPAD 640
#define NKC  40
#define CHUNK_BYTES (MPAD * 32)   // 20480
#define BQ_B  32400               // 25 rows x 648 halves x 2B
#define AT1S  632

#define OFT_TE  400000
#define OFT_AM  32400000
#define OFT_CLS 32450000

__device__ __align__(16) unsigned char g_Ah[NKC * CHUNK_BYTES];
__device__ __align__(16) float g_att1[QQ * AT1S];
__device__ float g_part[200 * SS];

// ---------------- smem layout (cam_main) — identical to R9 ----------------
#define OB_A     0        // 81920: A ring 4x20480; later G fp16 2x32512; later fq1/out1 staging
#define OB_B     81920    // 64800: B slots q*32400; later fq0/out0 staging (64000)
#define OB_AT1   146720   // 2 x 632 x 4
#define OB_ATT   151776   // 2 x 625 x 4
#define OB_KN    156776   // 16 x 112 x 4 = 7168 (doubles as GEMM zero-row)
#define OB_W1F   163944
#define OB_W2    164444
#define OB_B1F   164944
#define OB_B2S   164964
#define OB_NINV  165064   // 2 x 25 f
#define OB_TS    165264   // 2 x 25 f
#define OB_MBAR  165472   // 8 mbarriers
#define SMEM_BYTES 165536

#define GH_STRIDE 32512

#define AT1I (OB_AT1/4)
#define ATI  (OB_ATT/4)
#define KNI  (OB_KN/4)

__device__ __forceinline__ float warp_sum(float v) {
    #pragma unroll
    for (int o = 16; o; o >>= 1) v += __shfl_xor_sync(0xffffffffu, v, o);
    return v;
}
__device__ __forceinline__ void mbar_init(uint32_t mbar, uint32_t cnt) {
    asm volatile("mbarrier.init.shared.b64 [%0], %1;" :: "r"(mbar), "r"(cnt) : "memory");
}
__device__ __forceinline__ void mbar_expect_tx(uint32_t mbar, uint32_t bytes) {
    asm volatile("mbarrier.arrive.expect_tx.shared.b64 _, [%0], %1;"
                 :: "r"(mbar), "r"(bytes) : "memory");
}
__device__ __forceinline__ void mbar_wait(uint32_t mbar, uint32_t parity) {
    asm volatile(
        "{\n\t.reg .pred P;\n\t"
        "W_%=:\n\t"
        "mbarrier.try_wait.parity.acquire.cta.shared::cta.b64 P, [%0], %1, 0x989680;\n\t"
        "@P bra D_%=;\n\t"
        "bra.uni W_%=;\n\t"
        "D_%=:\n\t}"
        :: "r"(mbar), "r"(parity) : "memory");
}
__device__ __forceinline__ void bulk_ld(uint32_t dst, const void* src, uint32_t bytes,
                                        uint32_t mbar) {
    asm volatile("cp.async.bulk.shared::cluster.global.mbarrier::complete_tx::bytes "
                 "[%0], [%1], %2, [%3];"
                 :: "r"(dst), "l"(src), "r"(bytes), "r"(mbar) : "memory");
}
__device__ __forceinline__ void bulk_st(void* gdst, uint32_t ssrc, uint32_t bytes) {
    asm volatile("cp.async.bulk.global.shared::cta.bulk_group [%0], [%1], %2;"
                 :: "l"(gdst), "r"(ssrc), "r"(bytes) : "memory");
}
#define BULK_COMMIT() asm volatile("cp.async.bulk.commit_group;" ::: "memory")
#define BULK_WAIT0()  asm volatile("cp.async.bulk.wait_group 0;" ::: "memory")
#define FENCE_ASYNC() asm volatile("fence.proxy.async.shared::cta;" ::: "memory")

__device__ __forceinline__ void ldsm_x4(uint32_t& r0, uint32_t& r1, uint32_t& r2, uint32_t& r3,
                                        uint32_t addr) {
    asm volatile("ldmatrix.sync.aligned.m8n8.x4.shared.b16 {%0,%1,%2,%3}, [%4];"
                 : "=r"(r0), "=r"(r1), "=r"(r2), "=r"(r3) : "r"(addr));
}
__device__ __forceinline__ void mma16816h(uint32_t& d0, uint32_t& d1,
                                          uint32_t a0, uint32_t a1, uint32_t a2, uint32_t a3,
                                          uint32_t b0, uint32_t b1) {
    asm volatile("mma.sync.aligned.m16n8k16.row.col.f16.f16.f16.f16 "
                 "{%0,%1}, {%2,%3,%4,%5}, {%6,%7}, {%0,%1};"
                 : "+r"(d0), "+r"(d1)
                 : "r"(a0), "r"(a1), "r"(a2), "r"(a3), "r"(b0), "r"(b1));
}

// ---------------- K1: build swizzled fp16 A image ----------------
__global__ void __launch_bounds__(256) cam_prep_A(const float* __restrict__ ftrain) {
    extern __shared__ float sm[];
    float* xs    = sm;
    float* inv_s = sm + 16000;
    unsigned char* buf = (unsigned char*)sm + 64128;
    int p = blockIdx.x, tid = threadIdx.x, lane = tid & 31, w = tid >> 5;
    const float4* fp4 = (const float4*)(ftrain + p * TILE);
    float4* xs4 = (float4*)xs;
    for (int i = tid; i < 4000; i += 256) xs4[i] = fp4[i];
    __syncthreads();
    for (int s = w; s < SS; s += 8) {
        float acc = 0.f;
        #pragma unroll
        for (int k = 0; k < 20; k++) { float v = xs[(lane + 32 * k) * SS + s]; acc += v * v; }
        acc = warp_sum(acc);
        if (lane == 0) inv_s[s] = 1.f / fmaxf(sqrtf(acc), 1e-12f);
    }
    __syncthreads();
    for (int idx = tid; idx < TILE; idx += 256) {
        int c = idx / SS, s = idx - c * SS;
        __half v = __float2half_rn(xs[idx] * inv_s[s]);
        int m = p * SS + s;
        int kc = c >> 4, k = c & 15;
        uint32_t off = (uint32_t)((((k >> 3) ^ ((m >> 2) & 1)) << 4) + ((k & 7) << 1));
        *(__half*)(buf + kc * 800 + s * 32 + off) = v;
    }
    __syncthreads();
    for (int i = tid; i < 2000; i += 256) {
        int kc = i / 50, j = i - kc * 50;
        *(float4*)(g_Ah + (size_t)(kc * MPAD + p * SS) * 32 + j * 16) =
            *(const float4*)(buf + kc * 800 + j * 16);
    }
}

// ---------------- K2: main kernel, 2 q per CTA, packed N=56 GEMM ----------------
__global__ void __launch_bounds__(512, 1) cam_main(
    const float* __restrict__ ftest,
    const float* __restrict__ conv1_w, const float* __restrict__ conv1_b,
    const float* __restrict__ bn_gamma, const float* __restrict__ bn_beta,
    const float* __restrict__ bn_mean, const float* __restrict__ bn_var,
    const float* __restrict__ conv2_w, const float* __restrict__ conv2_b,
    float* __restrict__ out)
{
    extern __shared__ char smraw[];
    float* smf = (float*)smraw;
    const int tid = threadIdx.x, lane = tid & 31, w = tid >> 5;
    const int h = w >> 3;                 // half index (used after GEMM)
    const int wl = w & 7;
    const int q0 = blockIdx.x * 2;
    const int q = q0 + h;
    const uint32_t smb = (uint32_t)__cvta_generic_to_shared(smraw);
    const uint32_t MB = smb + OB_MBAR;

    if (tid == 0) {
        #pragma unroll
        for (int b = 0; b < 8; b++) mbar_init(MB + b * 8, 1);
    }
    for (int i = tid; i < 125; i += 512) {
        int cc = i / 25;
        smf[OB_W1F/4 + i] = conv1_w[i] * bn_gamma[cc] * rsqrtf(bn_var[cc] + 1e-5f);
        smf[OB_W2/4 + i]  = conv2_w[i];
    }
    if (tid < 5) {
        float scv = bn_gamma[tid] * rsqrtf(bn_var[tid] + 1e-5f);
        smf[OB_B1F/4 + tid] = (conv1_b[tid] - bn_mean[tid]) * scv + bn_beta[tid];
    }
    if (tid < 25) smf[OB_B2S/4 + tid] = conv2_b[tid];
    // zero the KN region head: serves as the GEMM zero-row (reads up to 1268 B)
    for (int i = tid; i < 328; i += 512) *(uint32_t*)(smraw + OB_KN + i * 4) = 0u;
    __syncthreads();   // mbarrier init + zero row visible

    // ---- setup: stage fq (bulk), norms, build B (2 q) ----
    for (int qi = 0; qi < 2; qi++) {
        if (tid == 0) {
            mbar_expect_tx(MB + (4 + qi) * 8, TILE * 4);
            bulk_ld(smb + OB_A, ftest + (size_t)(q0 + qi) * TILE, TILE * 4, MB + (4 + qi) * 8);
        }
        mbar_wait(MB + (4 + qi) * 8, 0);
        const float* fqs = (const float*)(smraw + OB_A);
        for (int s = w; s < SS; s += 16) {
            float acc = 0.f;
            #pragma unroll
            for (int k = 0; k < 20; k++) { float v = fqs[(lane + 32 * k) * SS + s]; acc += v * v; }
            acc = warp_sum(acc);
            if (lane == 0) smf[OB_NINV/4 + qi * 25 + s] = 1.f / fmaxf(sqrtf(acc), 1e-12f);
        }
        __syncthreads();
        for (int i = tid; i < 8000; i += 512) {
            int s = i / 320, c2 = i - s * 320;
            float iv = smf[OB_NINV/4 + qi * 25 + s];
            __half2 v = __floats2half2_rn(fqs[(2 * c2) * SS + s] * iv,
                                          fqs[(2 * c2 + 1) * SS + s] * iv);
            *(__half2*)(smraw + OB_B + qi * BQ_B + (s * 648 + 2 * c2) * 2) = v;
        }
        __syncthreads();
    }

    // ---- start A stream (bulk ring 4, prefetch 3) ----
    if (tid == 0) {
        #pragma unroll
        for (int pc = 0; pc < 3; pc++) {
            mbar_expect_tx(MB + pc * 8, CHUNK_BYTES);
            bulk_ld(smb + OB_A + pc * CHUNK_BYTES, g_Ah + (size_t)pc * CHUNK_BYTES,
                    CHUNK_BYTES, MB + pc * 8);
        }
    }

    // per-lane B bases for 7 n-tiles (rows 0..55; rows 50..55 -> zero row in KN)
    uint32_t bbase[7];
    #pragma unroll
    for (int nt = 0; nt < 7; nt++) {
        int rn = nt * 8 + (lane >> 2);
        if (rn < 50) {
            int qq = rn / 25, r = rn - qq * 25;
            bbase[nt] = (uint32_t)(OB_B + qq * BQ_B + r * 1296 + (lane & 3) * 4);
        } else {
            bbase[nt] = (uint32_t)(OB_KN + (lane & 3) * 4);
        }
    }

    // m-tiles: warps 0-7: {w, w+16, w+32}; warps 8-15: {w, w+16}
    const int nmt = (w < 8) ? 3 : 2;
    uint32_t hacc0[3][7], hacc1[3][7];
    #pragma unroll
    for (int j = 0; j < 3; j++)
        #pragma unroll
        for (int nt = 0; nt < 7; nt++) { hacc0[j][nt] = 0u; hacc1[j][nt] = 0u; }

    for (int i = 0; i < NKC; i++) {
        __syncthreads();                          // reads of slot (i+3)&3 done
        if (tid == 0 && i + 3 < NKC) {
            int b = (i + 3) & 3;
            mbar_expect_tx(MB + b * 8, CHUNK_BYTES);
            bulk_ld(smb + OB_A + b * CHUNK_BYTES, g_Ah + (size_t)(i + 3) * CHUNK_BYTES,
                    CHUNK_BYTES, MB + b * 8);
        }
        mbar_wait(MB + (i & 3) * 8, (i >> 2) & 1);
        const uint32_t abase = smb + OB_A + (i & 3) * CHUNK_BYTES;

        uint32_t af[3][4];
        #pragma unroll
        for (int j = 0; j < 3; j++) {
            if (j >= nmt) break;
            int m = (w + 16 * j) * 16 + (lane & 15);
            uint32_t addr = abase + m * 32 + ((((lane >> 4) ^ (m >> 2)) & 1) << 4);
            ldsm_x4(af[j][0], af[j][1], af[j][2], af[j][3], addr);
        }
        const uint32_t koff = (uint32_t)(i * 32);
        #pragma unroll
        for (int nt = 0; nt < 7; nt++) {
            uint32_t b0 = *(const uint32_t*)(smraw + bbase[nt] + koff);
            uint32_t b1 = *(const uint32_t*)(smraw + bbase[nt] + koff + 16);
            mma16816h(hacc0[0][nt], hacc1[0][nt], af[0][0], af[0][1], af[0][2], af[0][3], b0, b1);
            mma16816h(hacc0[1][nt], hacc1[1][nt], af[1][0], af[1][1], af[1][2], af[1][3], b0, b1);
            if (nmt == 3)
                mma16816h(hacc0[2][nt], hacc1[2][nt], af[2][0], af[2][1], af[2][2], af[2][3], b0, b1);
        }
    }
    __syncthreads();   // ring + B operands dead

    // prefetch raw fq0 for output into B region (overlaps epilogue)
    if (tid == 0) {
        mbar_expect_tx(MB + 6 * 8, TILE * 4);
        bulk_ld(smb + OB_B, ftest + (size_t)q0 * TILE, TILE * 4, MB + 6 * 8);
    }

    // ---- store G (fp16, 2 q slots over dead A region) ----
    #pragma unroll
    for (int j = 0; j < 3; j++) {
        if (j >= nmt) break;
        int r0 = (w + 16 * j) * 16 + (lane >> 2);
        int r1 = r0 + 8;
        #pragma unroll
        for (int nt = 0; nt < 7; nt++) {
            int cg = nt * 8 + (lane & 3) * 2;
            __half2 v0 = *reinterpret_cast<__half2*>(&hacc0[j][nt]);
            __half2 v1 = *reinterpret_cast<__half2*>(&hacc1[j][nt]);
            #pragma unroll
            for (int e = 0; e < 2; e++) {
                int cge = cg + e;
                if (cge < 50) {
                    int qq = cge / 25, c = cge - qq * 25;
                    __half* gq = (__half*)(smraw + OB_A + qq * GH_STRIDE);
                    __half h0 = (e == 0) ? __low2half(v0) : __high2half(v0);
                    __half h1 = (e == 0) ? __low2half(v1) : __high2half(v1);
                    if (r0 < 625) gq[r0 * 26 + c] = h0;
                    if (r1 < 625) gq[r1 * 26 + c] = h1;
                }
            }
        }
    }
    __syncthreads();

    // ---- per-(q,p) epilogue: 50 tasks over 16 warps ----
    for (int task = w; task < 50; task += 16) {
        int qq = task / 25, p = task - qq * 25;
        const __half* gh = (const __half*)(smraw + OB_A + qq * GH_STRIDE);
        float* kn = smf + KNI + w * 112;
        if (lane < 25) {
            float a1 = 0.f, a2 = 0.f;
            int rowb = (p * 25 + lane) * 26;
            int colb = p * 25 * 26 + lane;
            #pragma unroll
            for (int j = 0; j < 25; j++) {
                a1 += __half2float(gh[rowb + j]);
                a2 += __half2float(gh[colb + j * 26]);
            }
            kn[lane]      = a1 * (1.f / 25.f);
            kn[25 + lane] = a2 * (1.f / 25.f);
        }
        __syncwarp();
        if (lane < 5) {
            float a = smf[OB_B1F/4 + lane];
            #pragma unroll
            for (int j = 0; j < 25; j++) a += kn[j] * smf[OB_W1F/4 + lane * 25 + j];
            kn[50 + lane] = fmaxf(a, 0.f);
        } else if (lane >= 8 && lane < 13) {
            int ii = lane - 8;
            float a = smf[OB_B1F/4 + ii];
            #pragma unroll
            for (int j = 0; j < 25; j++) a += kn[25 + j] * smf[OB_W1F/4 + ii * 25 + j];
            kn[55 + ii] = fmaxf(a, 0.f);
        }
        __syncwarp();
        if (lane < 25) {
            float a1 = smf[OB_B2S/4 + lane], a2 = a1;
            #pragma unroll
            for (int ii = 0; ii < 5; ii++) {
                float wv = smf[OB_W2/4 + lane * 5 + ii];
                a1 += kn[50 + ii] * wv;
                a2 += kn[55 + ii] * wv;
            }
            kn[60 + lane] = fmaxf(a1, 0.f);
            kn[85 + lane] = fmaxf(a2, 0.f);
        }
        __syncwarp();
        if (lane < 25) {
            float att1 = 0.f, attt = 0.f;
            int colb = p * 25 * 26 + lane;
            int rowb = (p * 25 + lane) * 26;
            #pragma unroll
            for (int j = 0; j < 25; j++) {
                att1 += kn[60 + j] * __half2float(gh[colb + j * 26]);
                attt += __half2float(gh[rowb + j]) * kn[85 + j];
            }
            smf[AT1I + qq * AT1S + p * 25 + lane] = att1;
            smf[ATI + qq * 625 + p * 25 + lane]   = attt;
        }
    }
    __syncthreads();   // epilogue done; G dead

    // prefetch raw fq1 for output into A region
    if (tid == 0) {
        mbar_expect_tx(MB + 7 * 8, TILE * 4);
        bulk_ld(smb + OB_A, ftest + (size_t)(q0 + 1) * TILE, TILE * 4, MB + 7 * 8);
    }

    // ---- softmaxes (per half: wl==0 am, wl==1 cls) ----
    if (wl == 0) {
        float val = 0.f;
        if (lane < 25) {
            #pragma unroll
            for (int j = 0; j < 25; j++) val += smf[ATI + h * 625 + j * 25 + lane];
            val *= (1.f / 25.f);
        }
        float m = (lane < 25) ? val : -1e30f;
        #pragma unroll
        for (int o = 16; o; o >>= 1) m = fmaxf(m, __shfl_xor_sync(0xffffffffu, m, o));
        float e = (lane < 25) ? expf(val - m) : 0.f;
        float ssum = e;
        #pragma unroll
        for (int o = 16; o; o >>= 1) ssum += __shfl_xor_sync(0xffffffffu, ssum, o);
        float a = e / ssum;
        if (lane < 25) {
            out[OFT_AM + q * SS + lane] = a;
            smf[OB_TS/4 + h * 25 + lane] = a + 1.f;
        }
    } else if (wl == 1) {
        float rs = 0.f;
        if (lane < 25) {
            #pragma unroll
            for (int j = 0; j < 25; j++) rs += smf[ATI + h * 625 + lane * 25 + j];
        }
        int g = (lane < 5) ? lane : 4;
        float cg = 0.f;
        #pragma unroll
        for (int i = 0; i < 5; i++) cg += __shfl_sync(0xffffffffu, rs, g * 5 + i);
        cg *= (1.f / 125.f);
        float m = (lane < 5) ? cg : -1e30f;
        #pragma unroll
        for (int o = 4; o; o >>= 1) m = fmaxf(m, __shfl_xor_sync(0xffffffffu, m, o));
        float e = (lane < 5) ? expf(cg - m) : 0.f;
        float ssum = e;
        #pragma unroll
        for (int o = 4; o; o >>= 1) ssum += __shfl_xor_sync(0xffffffffu, ssum, o);
        if (lane < 5) out[OFT_CLS + q * 5 + lane] = e / ssum;
    }
    asm volatile("bar.sync %0, 256;" :: "r"(h + 1) : "memory");  // TS[h] ready

    // ---- output: half h scales its fq in smem, bulk-stores out + att1 ----
    {
        const uint32_t stage_off = (h == 0) ? OB_B : OB_A;
        mbar_wait(MB + (6 + h) * 8, 0);
        float4* st4 = (float4*)(smraw + stage_off);
        const int t2 = tid & 255;
        for (int i = t2; i < 4000; i += 256) {
            float4 b = st4[i];
            int s = (i * 4) % 25;
            b.x *= smf[OB_TS/4 + h * 25 + s]; s = (s == 24) ? 0 : s + 1;
            b.y *= smf[OB_TS/4 + h * 25 + s]; s = (s == 24) ? 0 : s + 1;
            b.z *= smf[OB_TS/4 + h * 25 + s]; s = (s == 24) ? 0 : s + 1;
            b.w *= smf[OB_TS/4 + h * 25 + s];
            st4[i] = b;
        }
        asm volatile("bar.sync %0, 256;" :: "r"(h + 1) : "memory");
        if (t2 == 0) {
            FENCE_ASYNC();
            bulk_st(out + OFT_TE + (size_t)q * TILE, smb + stage_off, TILE * 4);
            bulk_st(g_att1 + (size_t)q * AT1S, smb + OB_AT1 + h * (AT1S * 4), AT1S * 4);
            BULK_COMMIT();
            BULK_WAIT0();
        }
    }
    __syncthreads();   // keep smem alive until bulk stores complete
}

// ---------------- K3a: partial reduce of att1 over q slices ----------------
__global__ void __launch_bounds__(128) cam_final1() {
    __shared__ float red[125];
    int p = blockIdx.x >> 3, sl = blockIdx.x & 7;
    int tid = threadIdx.x;
    if (tid < 125) {
        int s = tid % 25, grp = tid / 25;
        const float* base = g_att1 + p * 25 + s;
        float acc = 0.f;
        for (int qq = sl * 250 + grp; qq < (sl + 1) * 250; qq += 5)
            acc += base[(size_t)qq * AT1S];
        red[tid] = acc;
    }
    __syncthreads();
    if (tid < 25) {
        float v = red[tid] + red[25 + tid] + red[50 + tid] + red[75 + tid] + red[100 + tid];
        g_part[blockIdx.x * 25 + tid] = v;
    }
}

// ---------------- K3b: combine, softmax, ftrain_out ----------------
__global__ void __launch_bounds__(256) cam_final2(const float* __restrict__ ftrain,
                                                  float* __restrict__ out) {
    __shared__ float att_s[SS];
    int p = blockIdx.x, tid = threadIdx.x, lane = tid & 31, w = tid >> 5;
    if (w == 0) {
        float val = 0.f;
        if (lane < 25) {
            #pragma unroll
            for (int k = 0; k < 8; k++) val += g_part[(p * 8 + k) * 25 + lane];
            val *= (1.f / (float)QQ);
        }
        float m = (lane < 25) ? val : -1e30f;
        #pragma unroll
        for (int o = 16; o; o >>= 1) m = fmaxf(m, __shfl_xor_sync(0xffffffffu, m, o));
        float e = (lane < 25) ? expf(val - m) : 0.f;
        float ssum = e;
        #pragma unroll
        for (int o = 16; o; o >>= 1) ssum += __shfl_xor_sync(0xffffffffu, ssum, o);
        if (lane < 25) att_s[lane] = e / ssum + 1.f;
    }
    __syncthreads();
    const float4* fp4 = (const float4*)(ftrain + p * TILE);
    float4* outp = (float4*)(out + (size_t)p * TILE);
    for (int i = tid; i < 4000; i += 256) {
        float4 b = fp4[i];
        int s = (i * 4) % 25;
        float4 o;
        o.x = b.x * att_s[s]; s = (s == 24) ? 0 : s + 1;
        o.y = b.y * att_s[s]; s = (s == 24) ? 0 : s + 1;
        o.z = b.z * att_s[s]; s = (s == 24) ? 0 : s + 1;
        o.w = b.w * att_s[s];
        outp[i] = o;
    }
}

// ---------------- launch ----------------
extern "C" void kernel_launch(void* const* d_in, const int* in_sizes, int n_in,
                              void* d_out, int out_size) {
    const float* ftrain  = (const float*)d_in[0];
    const float* ftest   = (const float*)d_in[1];
    const float* conv1_w = (const float*)d_in[6];
    const float* conv1_b = (const float*)d_in[7];
    const float* bn_gamma= (const float*)d_in[8];
    const float* bn_beta = (const float*)d_in[9];
    const float* bn_mean = (const float*)d_in[10];
    const float* bn_var  = (const float*)d_in[11];
    const float* conv2_w = (const float*)d_in[12];
    const float* conv2_b = (const float*)d_in[13];
    float* out = (float*)d_out;

    const int prepA_smem = 64128 + 32000;
    cudaFuncSetAttribute(cam_prep_A, cudaFuncAttributeMaxDynamicSharedMemorySize, prepA_smem);
    cudaFuncSetAttribute(cam_main,   cudaFuncAttributeMaxDynamicSharedMemorySize, SMEM_BYTES);

    cam_prep_A<<<PP, 256, prepA_smem>>>(ftrain);
    cam_main<<<QQ / 2, 512, SMEM_BYTES>>>(ftest, conv1_w, conv1_b, bn_gamma, bn_beta,
                                          bn_mean, bn_var, conv2_w, conv2_b, out);
    cam_final1<<<200, 128>>>();
    cam_final2<<<PP, 256>>>(ftrain, out);
}

// round 14
// speedup vs baseline: 3.0101x; 1.1009x over previous
#include <cuda_runtime.h>
#include <cuda_fp16.h>
#include <math.h>
#include <stdint.h>

#define PP   25
#define QQ   2000
#define CC   640
#define SS   25
#define TILE 16000

#define MPAD 640
#define NKC  40                   // 16-half chunks in g_Ah
#define CHUNK_BYTES (MPAD * 32)   // 20480
#define PAIR_BYTES  (2 * CHUNK_BYTES) // 40960 (one ring slot)
#define BQ_B  32400
#define AT1S  632

#define OFT_TE  400000
#define OFT_AM  32400000
#define OFT_CLS 32450000

__device__ __align__(16) unsigned char g_Ah[NKC * CHUNK_BYTES];
__device__ __align__(16) float g_att1[QQ * AT1S];
__device__ float g_part[200 * SS];

// ---------------- smem layout (cam_main) ----------------
#define OB_A     0        // 81920: A ring 2x40960; later G fp16 2x32512; later fq1/out1 staging
#define OB_B     81920    // 64800: B slots q*32400; later fq0/out0 staging (64000)
#define OB_AT1   146720
#define OB_ATT   151776
#define OB_KN    156776
#define OB_W1F   163944
#define OB_W2    164444
#define OB_B1F   164944
#define OB_B2S   164964
#define OB_NINV  165064
#define OB_TS    165264
#define OB_MBAR  165472   // 8 mbarriers
#define SMEM_BYTES 165536

#define GH_STRIDE 32512

#define AT1I (OB_AT1/4)
#define ATI  (OB_ATT/4)
#define KNI  (OB_KN/4)

__device__ __forceinline__ float warp_sum(float v) {
    #pragma unroll
    for (int o = 16; o; o >>= 1) v += __shfl_xor_sync(0xffffffffu, v, o);
    return v;
}
__device__ __forceinline__ void mbar_init(uint32_t mbar, uint32_t cnt) {
    asm volatile("mbarrier.init.shared.b64 [%0], %1;" :: "r"(mbar), "r"(cnt) : "memory");
}
__device__ __forceinline__ void mbar_expect_tx(uint32_t mbar, uint32_t bytes) {
    asm volatile("mbarrier.arrive.expect_tx.shared.b64 _, [%0], %1;"
                 :: "r"(mbar), "r"(bytes) : "memory");
}
__device__ __forceinline__ void mbar_wait(uint32_t mbar, uint32_t parity) {
    asm volatile(
        "{\n\t.reg .pred P;\n\t"
        "W_%=:\n\t"
        "mbarrier.try_wait.parity.acquire.cta.shared::cta.b64 P, [%0], %1, 0x989680;\n\t"
        "@P bra D_%=;\n\t"
        "bra.uni W_%=;\n\t"
        "D_%=:\n\t}"
        :: "r"(mbar), "r"(parity) : "memory");
}
__device__ __forceinline__ void bulk_ld(uint32_t dst, const void* src, uint32_t bytes,
                                        uint32_t mbar) {
    asm volatile("cp.async.bulk.shared::cluster.global.mbarrier::complete_tx::bytes "
                 "[%0], [%1], %2, [%3];"
                 :: "r"(dst), "l"(src), "r"(bytes), "r"(mbar) : "memory");
}
__device__ __forceinline__ void bulk_st(void* gdst, uint32_t ssrc, uint32_t bytes) {
    asm volatile("cp.async.bulk.global.shared::cta.bulk_group [%0], [%1], %2;"
                 :: "l"(gdst), "r"(ssrc), "r"(bytes) : "memory");
}
#define BULK_COMMIT() asm volatile("cp.async.bulk.commit_group;" ::: "memory")
#define BULK_WAIT0()  asm volatile("cp.async.bulk.wait_group 0;" ::: "memory")
#define FENCE_ASYNC() asm volatile("fence.proxy.async.shared::cta;" ::: "memory")

__device__ __forceinline__ void ldsm_x4(uint32_t& r0, uint32_t& r1, uint32_t& r2, uint32_t& r3,
                                        uint32_t addr) {
    asm volatile("ldmatrix.sync.aligned.m8n8.x4.shared.b16 {%0,%1,%2,%3}, [%4];"
                 : "=r"(r0), "=r"(r1), "=r"(r2), "=r"(r3) : "r"(addr));
}
__device__ __forceinline__ void mma16816h(uint32_t& d0, uint32_t& d1,
                                          uint32_t a0, uint32_t a1, uint32_t a2, uint32_t a3,
                                          uint32_t b0, uint32_t b1) {
    asm volatile("mma.sync.aligned.m16n8k16.row.col.f16.f16.f16.f16 "
                 "{%0,%1}, {%2,%3,%4,%5}, {%6,%7}, {%0,%1};"
                 : "+r"(d0), "+r"(d1)
                 : "r"(a0), "r"(a1), "r"(a2), "r"(a3), "r"(b0), "r"(b1));
}

// ---------------- K1: build swizzled fp16 A image ----------------
__global__ void __launch_bounds__(256) cam_prep_A(const float* __restrict__ ftrain) {
    extern __shared__ float sm[];
    float* xs    = sm;
    float* inv_s = sm + 16000;
    unsigned char* buf = (unsigned char*)sm + 64128;
    int p = blockIdx.x, tid = threadIdx.x, lane = tid & 31, w = tid >> 5;
    const float4* fp4 = (const float4*)(ftrain + p * TILE);
    float4* xs4 = (float4*)xs;
    for (int i = tid; i < 4000; i += 256) xs4[i] = fp4[i];
    __syncthreads();
    for (int s = w; s < SS; s += 8) {
        float acc = 0.f;
        #pragma unroll
        for (int k = 0; k < 20; k++) { float v = xs[(lane + 32 * k) * SS + s]; acc += v * v; }
        acc = warp_sum(acc);
        if (lane == 0) inv_s[s] = 1.f / fmaxf(sqrtf(acc), 1e-12f);
    }
    __syncthreads();
    for (int idx = tid; idx < TILE; idx += 256) {
        int c = idx / SS, s = idx - c * SS;
        __half v = __float2half_rn(xs[idx] * inv_s[s]);
        int m = p * SS + s;
        int kc = c >> 4, k = c & 15;
        uint32_t off = (uint32_t)((((k >> 3) ^ ((m >> 2) & 1)) << 4) + ((k & 7) << 1));
        *(__half*)(buf + kc * 800 + s * 32 + off) = v;
    }
    __syncthreads();
    for (int i = tid; i < 2000; i += 256) {
        int kc = i / 50, j = i - kc * 50;
        *(float4*)(g_Ah + (size_t)(kc * MPAD + p * SS) * 32 + j * 16) =
            *(const float4*)(buf + kc * 800 + j * 16);
    }
}

// ---------------- K2: main kernel, 2 q per CTA, paired-chunk stream ----------------
__global__ void __launch_bounds__(512, 1) cam_main(
    const float* __restrict__ ftest,
    const float* __restrict__ conv1_w, const float* __restrict__ conv1_b,
    const float* __restrict__ bn_gamma, const float* __restrict__ bn_beta,
    const float* __restrict__ bn_mean, const float* __restrict__ bn_var,
    const float* __restrict__ conv2_w, const float* __restrict__ conv2_b,
    float* __restrict__ out)
{
    extern __shared__ char smraw[];
    float* smf = (float*)smraw;
    const int tid = threadIdx.x, lane = tid & 31, w = tid >> 5;
    const int h = w >> 3;
    const int wl = w & 7;
    const int q0 = blockIdx.x * 2;
    const int q = q0 + h;
    const uint32_t smb = (uint32_t)__cvta_generic_to_shared(smraw);
    const uint32_t MB = smb + OB_MBAR;

    if (tid == 0) {
        #pragma unroll
        for (int b = 0; b < 8; b++) mbar_init(MB + b * 8, 1);
    }
    for (int i = tid; i < 125; i += 512) {
        int cc = i / 25;
        smf[OB_W1F/4 + i] = conv1_w[i] * bn_gamma[cc] * rsqrtf(bn_var[cc] + 1e-5f);
        smf[OB_W2/4 + i]  = conv2_w[i];
    }
    if (tid < 5) {
        float scv = bn_gamma[tid] * rsqrtf(bn_var[tid] + 1e-5f);
        smf[OB_B1F/4 + tid] = (conv1_b[tid] - bn_mean[tid]) * scv + bn_beta[tid];
    }
    if (tid < 25) smf[OB_B2S/4 + tid] = conv2_b[tid];
    __syncthreads();   // mbarrier init visible

    // ---- setup: stage fq (bulk), norms, build B (2 q) ----
    for (int qi = 0; qi < 2; qi++) {
        if (tid == 0) {
            mbar_expect_tx(MB + (4 + qi) * 8, TILE * 4);
            bulk_ld(smb + OB_A, ftest + (size_t)(q0 + qi) * TILE, TILE * 4, MB + (4 + qi) * 8);
        }
        mbar_wait(MB + (4 + qi) * 8, 0);
        const float* fqs = (const float*)(smraw + OB_A);
        for (int s = w; s < SS; s += 16) {
            float acc = 0.f;
            #pragma unroll
            for (int k = 0; k < 20; k++) { float v = fqs[(lane + 32 * k) * SS + s]; acc += v * v; }
            acc = warp_sum(acc);
            if (lane == 0) smf[OB_NINV/4 + qi * 25 + s] = 1.f / fmaxf(sqrtf(acc), 1e-12f);
        }
        __syncthreads();
        for (int i = tid; i < 8000; i += 512) {
            int s = i / 320, c2 = i - s * 320;
            float iv = smf[OB_NINV/4 + qi * 25 + s];
            __half2 v = __floats2half2_rn(fqs[(2 * c2) * SS + s] * iv,
                                          fqs[(2 * c2 + 1) * SS + s] * iv);
            *(__half2*)(smraw + OB_B + qi * BQ_B + (s * 648 + 2 * c2) * 2) = v;
        }
        __syncthreads();
    }

    // ---- start A stream: 2-slot ring of chunk PAIRS (40960 B each) ----
    if (tid == 0) {
        #pragma unroll
        for (int pc = 0; pc < 2; pc++) {
            mbar_expect_tx(MB + pc * 8, PAIR_BYTES);
            bulk_ld(smb + OB_A + pc * PAIR_BYTES, g_Ah + (size_t)pc * PAIR_BYTES,
                    PAIR_BYTES, MB + pc * 8);
        }
    }

    // ---- GEMM: each warp 5 m-tiles x 4 n-tiles for its q; 2 chunks per iteration ----
    uint32_t hacc[5][4][2];
    #pragma unroll
    for (int t = 0; t < 5; t++)
        #pragma unroll
        for (int n = 0; n < 4; n++) { hacc[t][n][0] = 0u; hacc[t][n][1] = 0u; }

    const int nrow = lane >> 2;
    const int kq   = lane & 3;
    const uint32_t bqbase = OB_B + h * BQ_B;

    for (int it = 0; it < 20; it++) {
        mbar_wait(MB + (it & 1) * 8, (it >> 1) & 1);
        const uint32_t pbase = smb + OB_A + (it & 1) * PAIR_BYTES;

        #pragma unroll
        for (int c = 0; c < 2; c++) {
            const int i = it * 2 + c;              // global 16-half chunk index
            const uint32_t abase = pbase + c * CHUNK_BYTES;

            uint32_t bf[4][2];
            #pragma unroll
            for (int nt = 0; nt < 3; nt++) {
                int n = nt * 8 + nrow;
                uint32_t bidx = bqbase + (uint32_t)(n * 648 + i * 16 + kq * 2) * 2;
                bf[nt][0] = *(const uint32_t*)(smraw + bidx);
                bf[nt][1] = *(const uint32_t*)(smraw + bidx + 16);
            }
            if (nrow == 0) {
                uint32_t bidx = bqbase + (uint32_t)(24 * 648 + i * 16 + kq * 2) * 2;
                bf[3][0] = *(const uint32_t*)(smraw + bidx);
                bf[3][1] = *(const uint32_t*)(smraw + bidx + 16);
            } else {
                bf[3][0] = 0u; bf[3][1] = 0u;
            }

            #pragma unroll
            for (int j = 0; j < 5; j++) {
                int mt = wl + 8 * j;
                int m = mt * 16 + (lane & 15);
                uint32_t addr = abase + m * 32 + ((((lane >> 4) ^ (m >> 2)) & 1) << 4);
                uint32_t a0, a1, a2, a3;
                ldsm_x4(a0, a1, a2, a3, addr);
                #pragma unroll
                for (int nt = 0; nt < 4; nt++)
                    mma16816h(hacc[j][nt][0], hacc[j][nt][1],
                              a0, a1, a2, a3, bf[nt][0], bf[nt][1]);
            }
        }

        __syncthreads();   // all warps done reading this slot
        if (tid == 0 && it + 2 < 20) {
            int b = it & 1;
            mbar_expect_tx(MB + b * 8, PAIR_BYTES);
            bulk_ld(smb + OB_A + b * PAIR_BYTES, g_Ah + (size_t)(it + 2) * PAIR_BYTES,
                    PAIR_BYTES, MB + b * 8);
        }
    }
    __syncthreads();   // ring + B operands dead

    // prefetch raw fq0 for output into B region (overlaps epilogue)
    if (tid == 0) {
        mbar_expect_tx(MB + 6 * 8, TILE * 4);
        bulk_ld(smb + OB_B, ftest + (size_t)q0 * TILE, TILE * 4, MB + 6 * 8);
    }

    // ---- store G (fp16, per-half buffer in dead A region) ----
    {
        __half* gh = (__half*)(smraw + OB_A + h * GH_STRIDE);
        #pragma unroll
        for (int j = 0; j < 5; j++) {
            int mt = wl + 8 * j;
            int r0 = mt * 16 + (lane >> 2);
            int r1 = r0 + 8;
            #pragma unroll
            for (int nt = 0; nt < 4; nt++) {
                int c = nt * 8 + (lane & 3) * 2;
                if (c + 1 < 25) {
                    if (r0 < 625) *(uint32_t*)(gh + r0 * 26 + c) = hacc[j][nt][0];
                    if (r1 < 625) *(uint32_t*)(gh + r1 * 26 + c) = hacc[j][nt][1];
                } else if (c < 25) {
                    __half2 v0 = *reinterpret_cast<__half2*>(&hacc[j][nt][0]);
                    __half2 v1 = *reinterpret_cast<__half2*>(&hacc[j][nt][1]);
                    if (r0 < 625) gh[r0 * 26 + c] = __low2half(v0);
                    if (r1 < 625) gh[r1 * 26 + c] = __low2half(v1);
                }
            }
        }
    }
    asm volatile("bar.sync %0, 256;" :: "r"(h + 1) : "memory");

    // ---- per-p epilogue (halves parallel) ----
    {
        const __half* gh = (const __half*)(smraw + OB_A + h * GH_STRIDE);
        for (int p = wl; p < PP; p += 8) {
            float* kn = smf + KNI + w * 112;
            if (lane < 25) {
                float a1 = 0.f, a2 = 0.f;
                int rowb = (p * 25 + lane) * 26;
                int colb = p * 25 * 26 + lane;
                #pragma unroll
                for (int j = 0; j < 25; j++) {
                    a1 += __half2float(gh[rowb + j]);
                    a2 += __half2float(gh[colb + j * 26]);
                }
                kn[lane]      = a1 * (1.f / 25.f);
                kn[25 + lane] = a2 * (1.f / 25.f);
            }
            __syncwarp();
            if (lane < 5) {
                float a = smf[OB_B1F/4 + lane];
                #pragma unroll
                for (int j = 0; j < 25; j++) a += kn[j] * smf[OB_W1F/4 + lane * 25 + j];
                kn[50 + lane] = fmaxf(a, 0.f);
            } else if (lane >= 8 && lane < 13) {
                int ii = lane - 8;
                float a = smf[OB_B1F/4 + ii];
                #pragma unroll
                for (int j = 0; j < 25; j++) a += kn[25 + j] * smf[OB_W1F/4 + ii * 25 + j];
                kn[55 + ii] = fmaxf(a, 0.f);
            }
            __syncwarp();
            if (lane < 25) {
                float a1 = smf[OB_B2S/4 + lane], a2 = a1;
                #pragma unroll
                for (int ii = 0; ii < 5; ii++) {
                    float wv = smf[OB_W2/4 + lane * 5 + ii];
                    a1 += kn[50 + ii] * wv;
                    a2 += kn[55 + ii] * wv;
                }
                kn[60 + lane] = fmaxf(a1, 0.f);
                kn[85 + lane] = fmaxf(a2, 0.f);
            }
            __syncwarp();
            if (lane < 25) {
                float att1 = 0.f, attt = 0.f;
                int colb = p * 25 * 26 + lane;
                int rowb = (p * 25 + lane) * 26;
                #pragma unroll
                for (int j = 0; j < 25; j++) {
                    att1 += kn[60 + j] * __half2float(gh[colb + j * 26]);
                    attt += __half2float(gh[rowb + j]) * kn[85 + j];
                }
                smf[AT1I + h * AT1S + p * 25 + lane] = att1;
                smf[ATI + h * 625 + p * 25 + lane]   = attt;
            }
        }
    }
    __syncthreads();   // both halves done with G

    // prefetch raw fq1 for output into A region
    if (tid == 0) {
        mbar_expect_tx(MB + 7 * 8, TILE * 4);
        bulk_ld(smb + OB_A, ftest + (size_t)(q0 + 1) * TILE, TILE * 4, MB + 7 * 8);
    }

    // ---- softmaxes (per half) ----
    if (wl == 0) {
        float val = 0.f;
        if (lane < 25) {
            #pragma unroll
            for (int j = 0; j < 25; j++) val += smf[ATI + h * 625 + j * 25 + lane];
            val *= (1.f / 25.f);
        }
        float m = (lane < 25) ? val : -1e30f;
        #pragma unroll
        for (int o = 16; o; o >>= 1) m = fmaxf(m, __shfl_xor_sync(0xffffffffu, m, o));
        float e = (lane < 25) ? expf(val - m) : 0.f;
        float ssum = e;
        #pragma unroll
        for (int o = 16; o; o >>= 1) ssum += __shfl_xor_sync(0xffffffffu, ssum, o);
        float a = e / ssum;
        if (lane < 25) {
            out[OFT_AM + q * SS + lane] = a;
            smf[OB_TS/4 + h * 25 + lane] = a + 1.f;
        }
    } else if (wl == 1) {
        float rs = 0.f;
        if (lane < 25) {
            #pragma unroll
            for (int j = 0; j < 25; j++) rs += smf[ATI + h * 625 + lane * 25 + j];
        }
        int g = (lane < 5) ? lane : 4;
        float cg = 0.f;
        #pragma unroll
        for (int i = 0; i < 5; i++) cg += __shfl_sync(0xffffffffu, rs, g * 5 + i);
        cg *= (1.f / 125.f);
        float m = (lane < 5) ? cg : -1e30f;
        #pragma unroll
        for (int o = 4; o; o >>= 1) m = fmaxf(m, __shfl_xor_sync(0xffffffffu, m, o));
        float e = (lane < 5) ? expf(cg - m) : 0.f;
        float ssum = e;
        #pragma unroll
        for (int o = 4; o; o >>= 1) ssum += __shfl_xor_sync(0xffffffffu, ssum, o);
        if (lane < 5) out[OFT_CLS + q * 5 + lane] = e / ssum;
    }
    asm volatile("bar.sync %0, 256;" :: "r"(h + 1) : "memory");  // TS[h] ready

    // ---- output: half h scales its fq in smem, bulk-stores out + att1 ----
    {
        const uint32_t stage_off = (h == 0) ? OB_B : OB_A;
        mbar_wait(MB + (6 + h) * 8, 0);
        float4* st4 = (float4*)(smraw + stage_off);
        const int t2 = tid & 255;
        for (int i = t2; i < 4000; i += 256) {
            float4 b = st4[i];
            int s = (i * 4) % 25;
            b.x *= smf[OB_TS/4 + h * 25 + s]; s = (s == 24) ? 0 : s + 1;
            b.y *= smf[OB_TS/4 + h * 25 + s]; s = (s == 24) ? 0 : s + 1;
            b.z *= smf[OB_TS/4 + h * 25 + s]; s = (s == 24) ? 0 : s + 1;
            b.w *= smf[OB_TS/4 + h * 25 + s];
            st4[i] = b;
        }
        asm volatile("bar.sync %0, 256;" :: "r"(h + 1) : "memory");
        if (t2 == 0) {
            FENCE_ASYNC();
            bulk_st(out + OFT_TE + (size_t)q * TILE, smb + stage_off, TILE * 4);
            bulk_st(g_att1 + (size_t)q * AT1S, smb + OB_AT1 + h * (AT1S * 4), AT1S * 4);
            BULK_COMMIT();
            BULK_WAIT0();
        }
    }
    __syncthreads();   // keep smem alive until bulk stores complete
}

// ---------------- K3a: partial reduce of att1 over q slices ----------------
__global__ void __launch_bounds__(128) cam_final1() {
    __shared__ float red[125];
    int p = blockIdx.x >> 3, sl = blockIdx.x & 7;
    int tid = threadIdx.x;
    if (tid < 125) {
        int s = tid % 25, grp = tid / 25;
        const float* base = g_att1 + p * 25 + s;
        float acc = 0.f;
        for (int qq = sl * 250 + grp; qq < (sl + 1) * 250; qq += 5)
            acc += base[(size_t)qq * AT1S];
        red[tid] = acc;
    }
    __syncthreads();
    if (tid < 25) {
        float v = red[tid] + red[25 + tid] + red[50 + tid] + red[75 + tid] + red[100 + tid];
        g_part[blockIdx.x * 25 + tid] = v;
    }
}

// ---------------- K3b: combine, softmax, ftrain_out ----------------
__global__ void __launch_bounds__(256) cam_final2(const float* __restrict__ ftrain,
                                                  float* __restrict__ out) {
    __shared__ float att_s[SS];
    int p = blockIdx.x, tid = threadIdx.x, lane = tid & 31, w = tid >> 5;
    if (w == 0) {
        float val = 0.f;
        if (lane < 25) {
            #pragma unroll
            for (int k = 0; k < 8; k++) val += g_part[(p * 8 + k) * 25 + lane];
            val *= (1.f / (float)QQ);
        }
        float m = (lane < 25) ? val : -1e30f;
        #pragma unroll
        for (int o = 16; o; o >>= 1) m = fmaxf(m, __shfl_xor_sync(0xffffffffu, m, o));
        float e = (lane < 25) ? expf(val - m) : 0.f;
        float ssum = e;
        #pragma unroll
        for (int o = 16; o; o >>= 1) ssum += __shfl_xor_sync(0xffffffffu, ssum, o);
        if (lane < 25) att_s[lane] = e / ssum + 1.f;
    }
    __syncthreads();
    const float4* fp4 = (const float4*)(ftrain + p * TILE);
    float4* outp = (float4*)(out + (size_t)p * TILE);
    for (int i = tid; i < 4000; i += 256) {
        float4 b = fp4[i];
        int s = (i * 4) % 25;
        float4 o;
        o.x = b.x * att_s[s]; s = (s == 24) ? 0 : s + 1;
        o.y = b.y * att_s[s]; s = (s == 24) ? 0 : s + 1;
        o.z = b.z * att_s[s]; s = (s == 24) ? 0 : s + 1;
        o.w = b.w * att_s[s];
        outp[i] = o;
    }
}

// ---------------- launch ----------------
extern "C" void kernel_launch(void* const* d_in, const int* in_sizes, int n_in,
                              void* d_out, int out_size) {
    const float* ftrain  = (const float*)d_in[0];
    const float* ftest   = (const float*)d_in[1];
    const float* conv1_w = (const float*)d_in[6];
    const float* conv1_b = (const float*)d_in[7];
    const float* bn_gamma= (const float*)d_in[8];
    const float* bn_beta = (const float*)d_in[9];
    const float* bn_mean = (const float*)d_in[10];
    const float* bn_var  = (const float*)d_in[11];
    const float* conv2_w = (const float*)d_in[12];
    const float* conv2_b = (const float*)d_in[13];
    float* out = (float*)d_out;

    const int prepA_smem = 64128 + 32000;
    cudaFuncSetAttribute(cam_prep_A, cudaFuncAttributeMaxDynamicSharedMemorySize, prepA_smem);
    cudaFuncSetAttribute(cam_main,   cudaFuncAttributeMaxDynamicSharedMemorySize, SMEM_BYTES);

    cam_prep_A<<<PP, 256, prepA_smem>>>(ftrain);
    cam_main<<<QQ / 2, 512, SMEM_BYTES>>>(ftest, conv1_w, conv1_b, bn_gamma, bn_beta,
                                          bn_mean, bn_var, conv2_w, conv2_b, out);
    cam_final1<<<200, 128>>>();
    cam_final2<<<PP, 256>>>(ftrain, out);
}